// round 8
// baseline (speedup 1.0000x reference)
#include <cuda_runtime.h>
#include <cuda_bf16.h>
#include <math.h>

#define BMAX 4096
#define KP 2368          // 3*784 = 2352, padded to 37*64

// scratch (no allocations allowed)
__device__ __nv_bfloat16 g_A[BMAX * KP];      // [Ah | Ah | Al] per row, padded
__device__ __nv_bfloat16 g_B[256 * KP];       // [Bh | Bl | Bh] per row, padded
__device__ float g_part[2 * BMAX * 256];      // split-K partials
__device__ float g_vc[8];
__device__ float g_vs[8];

// ---------------------------------------------------------------------------
__device__ __forceinline__ void split_bf16(float x, __nv_bfloat16& h, __nv_bfloat16& l) {
    h = __float2bfloat16(x);
    l = __float2bfloat16(x - __bfloat162float(h));
}

// ---------------------------------------------------------------------------
__global__ void var_precompute_kernel(const float* __restrict__ var) {
    int i = threadIdx.x;
    if (i < 8) {
        float h = 0.5f * var[i];
        g_vc[i] = cosf(h);
        g_vs[i] = sinf(h);
    }
}

// ---------------------------------------------------------------------------
// Convert W1 [256][784] fp32 -> g_B split-bf16 layout. Each thread: 4 k's.
// ---------------------------------------------------------------------------
__global__ __launch_bounds__(256) void convert_w1_kernel(const float* __restrict__ W1) {
    int t = blockIdx.x * 256 + threadIdx.x;
    if (t >= 256 * 196) return;
    int n = t / 196;
    int kq = t - n * 196;
    int k = kq * 4;

    float4 w = *(const float4*)(W1 + n * 784 + k);
    __nv_bfloat16 h[4], l[4];
    split_bf16(w.x, h[0], l[0]);
    split_bf16(w.y, h[1], l[1]);
    split_bf16(w.z, h[2], l[2]);
    split_bf16(w.w, h[3], l[3]);

    uint2 hp, lp;
    {
        __nv_bfloat162 a(h[0], h[1]), b(h[2], h[3]);
        hp.x = *(unsigned*)&a; hp.y = *(unsigned*)&b;
        __nv_bfloat162 c(l[0], l[1]), d(l[2], l[3]);
        lp.x = *(unsigned*)&c; lp.y = *(unsigned*)&d;
    }
    __nv_bfloat16* row = g_B + n * KP;
    *(uint2*)(row + k)        = hp;   // Bh
    *(uint2*)(row + 784 + k)  = lp;   // Bl
    *(uint2*)(row + 1568 + k) = hp;   // Bh
    if (kq < 4) {
        *(uint2*)(row + 2352 + kq * 4) = make_uint2(0u, 0u);  // pad
    }
}

// ---------------------------------------------------------------------------
// Quanvolution: one thread = one (batch, patch). 16-amplitude exact sim in
// registers. Writes split-bf16 features into the A_cat layout.
// ---------------------------------------------------------------------------
__global__ void quanv_kernel(const float* __restrict__ x, int B) {
    int idx = blockIdx.x * blockDim.x + threadIdx.x;
    if (idx >= B * 196) return;
    int b = idx / 196;
    int p = idx - b * 196;
    int r = p / 14;
    int c = p - r * 14;

    const float* img = x + b * 784;
    float2 top = *(const float2*)(img + (2 * r) * 28 + 2 * c);
    float2 bot = *(const float2*)(img + (2 * r + 1) * 28 + 2 * c);
    float ang[4] = {top.x, top.y, bot.x, bot.y};

    float ec[4], es[4];
#pragma unroll
    for (int w = 0; w < 4; ++w) sincosf(0.5f * ang[w], &es[w], &ec[w]);

    float st[16];
#pragma unroll
    for (int i = 0; i < 16; ++i) {
        st[i] = ((i & 8) ? es[0] : ec[0]) * ((i & 4) ? es[1] : ec[1]) *
                ((i & 2) ? es[2] : ec[2]) * ((i & 1) ? es[3] : ec[3]);
    }

    float vc[8], vs[8];
#pragma unroll
    for (int i = 0; i < 8; ++i) { vc[i] = g_vc[i]; vs[i] = g_vs[i]; }

#pragma unroll
    for (int d = 0; d < 2; ++d) {
#pragma unroll
        for (int w = 0; w < 4; ++w) {
            float cc = vc[d * 4 + w];
            float ss = vs[d * 4 + w];
            int mask = 8 >> w;
#pragma unroll
            for (int i = 0; i < 16; ++i) {
                if (!(i & mask)) {
                    int j = i | mask;
                    float a = st[i], bb = st[j];
                    st[i] = cc * a - ss * bb;
                    st[j] = ss * a + cc * bb;
                }
            }
        }
#pragma unroll
        for (int cw = 0; cw < 4; ++cw) {
            int tw = (cw + 1) & 3;
            int cm = 8 >> cw;
            int tm = 8 >> tw;
#pragma unroll
            for (int i = 0; i < 16; ++i) {
                if ((i & cm) && !(i & tm)) {
                    int j = i | tm;
                    float t = st[i]; st[i] = st[j]; st[j] = t;
                }
            }
        }
    }

    float q[16];
#pragma unroll
    for (int i = 0; i < 16; ++i) q[i] = st[i] * st[i];

    float fo[4];
#pragma unroll
    for (int w = 0; w < 4; ++w) {
        int m = 8 >> w;
        float acc = 0.f;
#pragma unroll
        for (int i = 0; i < 16; ++i) acc += (i & m) ? -q[i] : q[i];
        fo[w] = acc;
    }

    __nv_bfloat16 fh[4], fl[4];
#pragma unroll
    for (int w = 0; w < 4; ++w) split_bf16(fo[w], fh[w], fl[w]);

    uint2 hp, lp;
    {
        __nv_bfloat162 a(fh[0], fh[1]), bb(fh[2], fh[3]);
        hp.x = *(unsigned*)&a; hp.y = *(unsigned*)&bb;
        __nv_bfloat162 cc(fl[0], fl[1]), dd(fl[2], fl[3]);
        lp.x = *(unsigned*)&cc; lp.y = *(unsigned*)&dd;
    }
    __nv_bfloat16* row = g_A + (size_t)b * KP;
    *(uint2*)(row + p * 4)        = hp;   // Ah
    *(uint2*)(row + 784 + p * 4)  = hp;   // Ah (pairs Bl)
    *(uint2*)(row + 1568 + p * 4) = lp;   // Al (pairs Bh)
    if (p < 4) {
        *(uint2*)(row + 2352 + p * 4) = make_uint2(0u, 0u);  // pad
    }
}

// ---------------------------------------------------------------------------
// Tensor-core GEMM1 (split-K=2): part[s] = A_cat[:, Ks] @ B_cat[:, Ks]^T.
// BM=64, BN=64, BK=64, 8 warps (4x2), warp tile 16x32 via m16n8k16 mma.
// 3-stage cp.async pipeline, one __syncthreads per iter. Grid (M/64, 4, 2).
// ---------------------------------------------------------------------------
#define GBK 64
#define NITER (KP / GBK)   // 37
#define SPLIT0 19          // chunks in split 0 (split 1 gets 18)
#define ASTRIDE 72         // 64 + 8 pad: 144B row stride, ldmatrix conflict-free

__device__ __forceinline__ void mma_bf16(float* c, const unsigned* a, const unsigned* b) {
    asm volatile(
        "mma.sync.aligned.m16n8k16.row.col.f32.bf16.bf16.f32 "
        "{%0,%1,%2,%3}, {%4,%5,%6,%7}, {%8,%9}, {%0,%1,%2,%3};\n"
        : "+f"(c[0]), "+f"(c[1]), "+f"(c[2]), "+f"(c[3])
        : "r"(a[0]), "r"(a[1]), "r"(a[2]), "r"(a[3]), "r"(b[0]), "r"(b[1]));
}

__global__ __launch_bounds__(256, 3) void gemm1_kernel() {
    __shared__ __nv_bfloat16 As[3][64][ASTRIDE];   // 27.6 KB
    __shared__ __nv_bfloat16 Bs[3][64][ASTRIDE];   // 27.6 KB (total 55.3 KB)

    int tid = threadIdx.x;
    int wid = tid >> 5;
    int lane = tid & 31;
    int warp_m = wid & 3;      // 0..3 -> m offset 16*warp_m
    int warp_n = wid >> 2;     // 0..1 -> n offset 32*warp_n
    int bm = blockIdx.x * 64;
    int bn = blockIdx.y * 64;
    int zs = blockIdx.z;
    int ch0 = zs ? SPLIT0 : 0;
    int cnt = zs ? (NITER - SPLIT0) : SPLIT0;

    float acc[4][4];
#pragma unroll
    for (int j = 0; j < 4; ++j)
#pragma unroll
        for (int k = 0; k < 4; ++k) acc[j][k] = 0.f;

    int r0 = tid >> 3, c0 = tid & 7;
    int r1 = (tid + 256) >> 3, c1 = c0;

#define LOAD_STAGE(CH, BUF)                                                      \
    do {                                                                         \
        int k0 = (CH) * GBK;                                                     \
        const __nv_bfloat16* s0 = g_A + (size_t)(bm + r0) * KP + k0 + c0 * 8;    \
        unsigned d0 = (unsigned)__cvta_generic_to_shared(&As[BUF][r0][c0 * 8]);  \
        asm volatile("cp.async.cg.shared.global [%0], [%1], 16;\n" ::"r"(d0), "l"(s0)); \
        const __nv_bfloat16* s1 = g_A + (size_t)(bm + r1) * KP + k0 + c1 * 8;    \
        unsigned d1 = (unsigned)__cvta_generic_to_shared(&As[BUF][r1][c1 * 8]);  \
        asm volatile("cp.async.cg.shared.global [%0], [%1], 16;\n" ::"r"(d1), "l"(s1)); \
        const __nv_bfloat16* s2 = g_B + (size_t)(bn + r0) * KP + k0 + c0 * 8;    \
        unsigned d2 = (unsigned)__cvta_generic_to_shared(&Bs[BUF][r0][c0 * 8]);  \
        asm volatile("cp.async.cg.shared.global [%0], [%1], 16;\n" ::"r"(d2), "l"(s2)); \
        const __nv_bfloat16* s3 = g_B + (size_t)(bn + r1) * KP + k0 + c1 * 8;    \
        unsigned d3 = (unsigned)__cvta_generic_to_shared(&Bs[BUF][r1][c1 * 8]);  \
        asm volatile("cp.async.cg.shared.global [%0], [%1], 16;\n" ::"r"(d3), "l"(s3)); \
    } while (0)

    LOAD_STAGE(ch0, 0);
    asm volatile("cp.async.commit_group;\n" ::);
    LOAD_STAGE(ch0 + 1, 1);
    asm volatile("cp.async.commit_group;\n" ::);

    int gid = lane >> 3;   // ldmatrix address group
    int wi = lane & 7;

    for (int it = 0; it < cnt; ++it) {
        int buf = it % 3;
        asm volatile("cp.async.wait_group 1;\n" ::);
        __syncthreads();   // stage `buf` ready; compute of it-1 fully retired

        if (it + 2 < cnt) LOAD_STAGE(ch0 + it + 2, (it + 2) % 3);
        asm volatile("cp.async.commit_group;\n" ::);

#pragma unroll
        for (int kk = 0; kk < 4; ++kk) {
            unsigned a[4];
            {
                int row = warp_m * 16 + (gid & 1) * 8 + wi;
                int col = kk * 16 + (gid >> 1) * 8;
                unsigned addr = (unsigned)__cvta_generic_to_shared(&As[buf][row][col]);
                asm volatile(
                    "ldmatrix.sync.aligned.m8n8.x4.shared.b16 {%0,%1,%2,%3}, [%4];\n"
                    : "=r"(a[0]), "=r"(a[1]), "=r"(a[2]), "=r"(a[3])
                    : "r"(addr));
            }
            unsigned b[4][2];
#pragma unroll
            for (int nh = 0; nh < 2; ++nh) {
                int row = warp_n * 32 + nh * 16 + (gid >> 1) * 8 + wi;
                int col = kk * 16 + (gid & 1) * 8;
                unsigned addr = (unsigned)__cvta_generic_to_shared(&Bs[buf][row][col]);
                asm volatile(
                    "ldmatrix.sync.aligned.m8n8.x4.shared.b16 {%0,%1,%2,%3}, [%4];\n"
                    : "=r"(b[2 * nh][0]), "=r"(b[2 * nh][1]),
                      "=r"(b[2 * nh + 1][0]), "=r"(b[2 * nh + 1][1])
                    : "r"(addr));
            }
#pragma unroll
            for (int nf = 0; nf < 4; ++nf) mma_bf16(acc[nf], a, b[nf]);
        }
    }

    // epilogue: raw fp32 partials (bias/relu applied in head)
    float* part = g_part + (size_t)zs * (BMAX * 256);
#pragma unroll
    for (int nf = 0; nf < 4; ++nf) {
        int n = bn + warp_n * 32 + nf * 8 + (lane & 3) * 2;
        int m = bm + warp_m * 16 + (lane >> 2);
        float2 o0, o1;
        o0.x = acc[nf][0]; o0.y = acc[nf][1];
        o1.x = acc[nf][2]; o1.y = acc[nf][3];
        *(float2*)(part + m * 256 + n) = o0;
        *(float2*)(part + (m + 8) * 256 + n) = o1;
    }
#undef LOAD_STAGE
}

// ---------------------------------------------------------------------------
// Head: h = relu(p0 + p1 + b1); logits = h @ W2^T + b2; log_softmax.
// 4 rows per warp.
// ---------------------------------------------------------------------------
__global__ __launch_bounds__(256) void head_kernel(const float* __restrict__ W2,
                                                   const float* __restrict__ b1,
                                                   const float* __restrict__ b2,
                                                   float* __restrict__ out, int B) {
    int warp = threadIdx.x >> 5;
    int lane = threadIdx.x & 31;
    int row0 = (blockIdx.x * 8 + warp) * 4;
    if (row0 >= B) return;

    const float* p0 = g_part;
    const float* p1 = g_part + BMAX * 256;

    float b1v[8];
#pragma unroll
    for (int j = 0; j < 8; ++j) b1v[j] = __ldg(b1 + lane + 32 * j);

    float hv[4][8];
#pragma unroll
    for (int r = 0; r < 4; ++r)
#pragma unroll
        for (int j = 0; j < 8; ++j) {
            int ix = (row0 + r) * 256 + lane + 32 * j;
            hv[r][j] = fmaxf(p0[ix] + p1[ix] + b1v[j], 0.f);
        }

    float lg[4][10];
#pragma unroll
    for (int o = 0; o < 10; ++o) {
        const float* w = W2 + o * 256;
        float wv[8];
#pragma unroll
        for (int j = 0; j < 8; ++j) wv[j] = __ldg(w + lane + 32 * j);
        float p[4] = {0.f, 0.f, 0.f, 0.f};
#pragma unroll
        for (int j = 0; j < 8; ++j)
#pragma unroll
            for (int r = 0; r < 4; ++r) p[r] += hv[r][j] * wv[j];
#pragma unroll
        for (int off = 16; off > 0; off >>= 1)
#pragma unroll
            for (int r = 0; r < 4; ++r) p[r] += __shfl_xor_sync(0xffffffffu, p[r], off);
        float bo = __ldg(b2 + o);
#pragma unroll
        for (int r = 0; r < 4; ++r) lg[r][o] = p[r] + bo;
    }

#pragma unroll
    for (int r = 0; r < 4; ++r) {
        float m = lg[r][0];
#pragma unroll
        for (int o = 1; o < 10; ++o) m = fmaxf(m, lg[r][o]);
        float sum = 0.f;
#pragma unroll
        for (int o = 0; o < 10; ++o) sum += expf(lg[r][o] - m);
        float lse = m + logf(sum);
        float myv = 0.f;
#pragma unroll
        for (int o = 0; o < 10; ++o)
            if (lane == o) myv = lg[r][o];
        if (lane < 10) out[(row0 + r) * 10 + lane] = myv - lse;
    }
}

// ---------------------------------------------------------------------------
extern "C" void kernel_launch(void* const* d_in, const int* in_sizes, int n_in,
                              void* d_out, int out_size) {
    const float* x   = (const float*)d_in[0];
    const float* var = (const float*)d_in[1];
    const float* W1  = (const float*)d_in[2];
    const float* b1  = (const float*)d_in[3];
    const float* W2  = (const float*)d_in[4];
    const float* b2  = (const float*)d_in[5];
    float* out = (float*)d_out;

    int B = in_sizes[0] / 784;

    var_precompute_kernel<<<1, 8>>>(var);
    convert_w1_kernel<<<(256 * 196 + 255) / 256, 256>>>(W1);

    int np = B * 196;
    quanv_kernel<<<(np + 255) / 256, 256>>>(x, B);

    dim3 g1(B / 64, 256 / 64, 2);
    gemm1_kernel<<<g1, 256>>>();

    // 8 warps/block, 4 rows/warp -> 32 rows per block
    int head_blocks = (B / 4 + 7) / 8;
    head_kernel<<<head_blocks, 256>>>(W2, b1, b2, out, B);
}

// round 9
// speedup vs baseline: 2.0274x; 2.0274x over previous
#include <cuda_runtime.h>
#include <cuda_fp16.h>
#include <math.h>

#define BMAX 4096
#define KP 800           // 784 padded to 25*32

// scratch (no allocations allowed)
__device__ __half g_A[BMAX * KP];     // feats fp16, padded
__device__ __half g_B[256 * KP];      // W1 fp16, padded
__device__ float g_h[BMAX * 256];
__device__ float g_vc[8];
__device__ float g_vs[8];

__device__ __forceinline__ unsigned pack_half2(__half a, __half b) {
    __half2 t = __halves2half2(a, b);
    return *(unsigned*)&t;
}

// ---------------------------------------------------------------------------
__global__ void var_precompute_kernel(const float* __restrict__ var) {
    int i = threadIdx.x;
    if (i < 8) {
        float h = 0.5f * var[i];
        g_vc[i] = cosf(h);
        g_vs[i] = sinf(h);
    }
}

// ---------------------------------------------------------------------------
// Convert W1 [256][784] fp32 -> g_B fp16 [256][800]. Each thread: 4 k's.
// ---------------------------------------------------------------------------
__global__ __launch_bounds__(256) void convert_w1_kernel(const float* __restrict__ W1) {
    int t = blockIdx.x * 256 + threadIdx.x;
    if (t >= 256 * 196) return;
    int n = t / 196;
    int kq = t - n * 196;
    int k = kq * 4;

    float4 w = *(const float4*)(W1 + n * 784 + k);
    uint2 hp;
    hp.x = pack_half2(__float2half_rn(w.x), __float2half_rn(w.y));
    hp.y = pack_half2(__float2half_rn(w.z), __float2half_rn(w.w));

    __half* row = g_B + n * KP;
    *(uint2*)(row + k) = hp;
    if (kq < 4) {
        *(uint2*)(row + 784 + kq * 4) = make_uint2(0u, 0u);  // pad
    }
}

// ---------------------------------------------------------------------------
// Quanvolution: one thread = one (batch, patch). 16-amplitude exact sim in
// registers. Writes fp16 features.
// ---------------------------------------------------------------------------
__global__ void quanv_kernel(const float* __restrict__ x, int B) {
    int idx = blockIdx.x * blockDim.x + threadIdx.x;
    if (idx >= B * 196) return;
    int b = idx / 196;
    int p = idx - b * 196;
    int r = p / 14;
    int c = p - r * 14;

    const float* img = x + b * 784;
    float2 top = *(const float2*)(img + (2 * r) * 28 + 2 * c);
    float2 bot = *(const float2*)(img + (2 * r + 1) * 28 + 2 * c);
    float ang[4] = {top.x, top.y, bot.x, bot.y};

    float ec[4], es[4];
#pragma unroll
    for (int w = 0; w < 4; ++w) sincosf(0.5f * ang[w], &es[w], &ec[w]);

    float st[16];
#pragma unroll
    for (int i = 0; i < 16; ++i) {
        st[i] = ((i & 8) ? es[0] : ec[0]) * ((i & 4) ? es[1] : ec[1]) *
                ((i & 2) ? es[2] : ec[2]) * ((i & 1) ? es[3] : ec[3]);
    }

    float vc[8], vs[8];
#pragma unroll
    for (int i = 0; i < 8; ++i) { vc[i] = g_vc[i]; vs[i] = g_vs[i]; }

#pragma unroll
    for (int d = 0; d < 2; ++d) {
#pragma unroll
        for (int w = 0; w < 4; ++w) {
            float cc = vc[d * 4 + w];
            float ss = vs[d * 4 + w];
            int mask = 8 >> w;
#pragma unroll
            for (int i = 0; i < 16; ++i) {
                if (!(i & mask)) {
                    int j = i | mask;
                    float a = st[i], bb = st[j];
                    st[i] = cc * a - ss * bb;
                    st[j] = ss * a + cc * bb;
                }
            }
        }
#pragma unroll
        for (int cw = 0; cw < 4; ++cw) {
            int tw = (cw + 1) & 3;
            int cm = 8 >> cw;
            int tm = 8 >> tw;
#pragma unroll
            for (int i = 0; i < 16; ++i) {
                if ((i & cm) && !(i & tm)) {
                    int j = i | tm;
                    float t = st[i]; st[i] = st[j]; st[j] = t;
                }
            }
        }
    }

    float q[16];
#pragma unroll
    for (int i = 0; i < 16; ++i) q[i] = st[i] * st[i];

    float fo[4];
#pragma unroll
    for (int w = 0; w < 4; ++w) {
        int m = 8 >> w;
        float acc = 0.f;
#pragma unroll
        for (int i = 0; i < 16; ++i) acc += (i & m) ? -q[i] : q[i];
        fo[w] = acc;
    }

    uint2 hp;
    hp.x = pack_half2(__float2half_rn(fo[0]), __float2half_rn(fo[1]));
    hp.y = pack_half2(__float2half_rn(fo[2]), __float2half_rn(fo[3]));

    __half* row = g_A + (size_t)b * KP;
    *(uint2*)(row + p * 4) = hp;
    if (p < 4) {
        *(uint2*)(row + 784 + p * 4) = make_uint2(0u, 0u);  // pad
    }
}

// ---------------------------------------------------------------------------
// Tensor-core GEMM1: h = relu(A @ B^T + b1).  M=B, N=256, K=800 (fp16).
// BM=128, BN=64, BK=32, 8 warps (4x2), warp tile 32x32 via m16n8k16 mma.
// 3-stage cp.async pipeline, ONE __syncthreads per k-iteration.
// ---------------------------------------------------------------------------
#define GBK 32
#define NITER (KP / GBK)   // 25
#define ASTRIDE 40         // padded row (conflict-free ldmatrix: 80B stride)

__device__ __forceinline__ void mma_f16(float* c, const unsigned* a, const unsigned* b) {
    asm volatile(
        "mma.sync.aligned.m16n8k16.row.col.f32.f16.f16.f32 "
        "{%0,%1,%2,%3}, {%4,%5,%6,%7}, {%8,%9}, {%0,%1,%2,%3};\n"
        : "+f"(c[0]), "+f"(c[1]), "+f"(c[2]), "+f"(c[3])
        : "r"(a[0]), "r"(a[1]), "r"(a[2]), "r"(a[3]), "r"(b[0]), "r"(b[1]));
}

__global__ __launch_bounds__(256, 1) void gemm1_kernel(const float* __restrict__ b1) {
    __shared__ __half As[3][128][ASTRIDE];   // 30.7 KB
    __shared__ __half Bs[3][64][ASTRIDE];    // 15.4 KB  (total 46 KB)

    int tid = threadIdx.x;
    int wid = tid >> 5;
    int lane = tid & 31;
    int warp_m = wid & 3;      // 0..3 -> m offset 32*warp_m
    int warp_n = wid >> 2;     // 0..1 -> n offset 32*warp_n
    int bm = blockIdx.x * 128;
    int bn = blockIdx.y * 64;

    float acc[2][4][4];
#pragma unroll
    for (int i = 0; i < 2; ++i)
#pragma unroll
        for (int j = 0; j < 4; ++j)
#pragma unroll
            for (int k = 0; k < 4; ++k) acc[i][j][k] = 0.f;

    // load-thread mapping: A = 128 rows x 4 chunks(16B), B = 64 rows x 4 chunks
    int a_r0 = tid >> 2;          // rows 0..63
    int a_c0 = tid & 3;
    int a_r1 = (tid + 256) >> 2;  // rows 64..127
    int a_c1 = a_c0;
    int b_r = tid >> 2;
    int b_c = tid & 3;

#define LOAD_STAGE(IT, BUF)                                                      \
    do {                                                                         \
        int k0 = (IT) * GBK;                                                     \
        const __half* s0 = g_A + (size_t)(bm + a_r0) * KP + k0 + a_c0 * 8;       \
        unsigned d0 = (unsigned)__cvta_generic_to_shared(&As[BUF][a_r0][a_c0*8]);\
        asm volatile("cp.async.cg.shared.global [%0], [%1], 16;\n" ::"r"(d0), "l"(s0)); \
        const __half* s1 = g_A + (size_t)(bm + a_r1) * KP + k0 + a_c1 * 8;       \
        unsigned d1 = (unsigned)__cvta_generic_to_shared(&As[BUF][a_r1][a_c1*8]);\
        asm volatile("cp.async.cg.shared.global [%0], [%1], 16;\n" ::"r"(d1), "l"(s1)); \
        const __half* s2 = g_B + (size_t)(bn + b_r) * KP + k0 + b_c * 8;         \
        unsigned d2 = (unsigned)__cvta_generic_to_shared(&Bs[BUF][b_r][b_c*8]);  \
        asm volatile("cp.async.cg.shared.global [%0], [%1], 16;\n" ::"r"(d2), "l"(s2)); \
    } while (0)

    LOAD_STAGE(0, 0);
    asm volatile("cp.async.commit_group;\n" ::);
    LOAD_STAGE(1, 1);
    asm volatile("cp.async.commit_group;\n" ::);

    int gid = lane >> 3;   // ldmatrix address group
    int wi = lane & 7;

    for (int it = 0; it < NITER; ++it) {
        int buf = it % 3;
        asm volatile("cp.async.wait_group 1;\n" ::);
        __syncthreads();   // stage `buf` ready; compute of it-1 fully retired

        if (it + 2 < NITER) LOAD_STAGE(it + 2, (it + 2) % 3);
        asm volatile("cp.async.commit_group;\n" ::);

#pragma unroll
        for (int kk = 0; kk < 2; ++kk) {
            unsigned a[2][4];
#pragma unroll
            for (int mf = 0; mf < 2; ++mf) {
                int row = warp_m * 32 + mf * 16 + (gid & 1) * 8 + wi;
                int col = kk * 16 + (gid >> 1) * 8;
                unsigned addr = (unsigned)__cvta_generic_to_shared(&As[buf][row][col]);
                asm volatile(
                    "ldmatrix.sync.aligned.m8n8.x4.shared.b16 {%0,%1,%2,%3}, [%4];\n"
                    : "=r"(a[mf][0]), "=r"(a[mf][1]), "=r"(a[mf][2]), "=r"(a[mf][3])
                    : "r"(addr));
            }
            unsigned b[4][2];
#pragma unroll
            for (int nh = 0; nh < 2; ++nh) {
                int row = warp_n * 32 + nh * 16 + (gid >> 1) * 8 + wi;
                int col = kk * 16 + (gid & 1) * 8;
                unsigned addr = (unsigned)__cvta_generic_to_shared(&Bs[buf][row][col]);
                asm volatile(
                    "ldmatrix.sync.aligned.m8n8.x4.shared.b16 {%0,%1,%2,%3}, [%4];\n"
                    : "=r"(b[2 * nh][0]), "=r"(b[2 * nh][1]),
                      "=r"(b[2 * nh + 1][0]), "=r"(b[2 * nh + 1][1])
                    : "r"(addr));
            }
#pragma unroll
            for (int mf = 0; mf < 2; ++mf)
#pragma unroll
                for (int nf = 0; nf < 4; ++nf) mma_f16(acc[mf][nf], a[mf], b[nf]);
        }
    }

    // epilogue: bias + relu, fp32 out
#pragma unroll
    for (int nf = 0; nf < 4; ++nf) {
        int n = bn + warp_n * 32 + nf * 8 + (lane & 3) * 2;
        float2 bias = *(const float2*)(b1 + n);
#pragma unroll
        for (int mf = 0; mf < 2; ++mf) {
            int m = bm + warp_m * 32 + mf * 16 + (lane >> 2);
            float2 o0, o1;
            o0.x = fmaxf(acc[mf][nf][0] + bias.x, 0.f);
            o0.y = fmaxf(acc[mf][nf][1] + bias.y, 0.f);
            o1.x = fmaxf(acc[mf][nf][2] + bias.x, 0.f);
            o1.y = fmaxf(acc[mf][nf][3] + bias.y, 0.f);
            *(float2*)(g_h + m * 256 + n) = o0;
            *(float2*)(g_h + (m + 8) * 256 + n) = o1;
        }
    }
#undef LOAD_STAGE
}

// ---------------------------------------------------------------------------
// Head: logits = h @ W2^T + b2, then log_softmax. 4 rows per warp.
// ---------------------------------------------------------------------------
__global__ __launch_bounds__(256) void head_kernel(const float* __restrict__ W2,
                                                   const float* __restrict__ b2,
                                                   float* __restrict__ out, int B) {
    int warp = threadIdx.x >> 5;
    int lane = threadIdx.x & 31;
    int row0 = (blockIdx.x * 8 + warp) * 4;
    if (row0 >= B) return;

    float hv[4][8];
#pragma unroll
    for (int r = 0; r < 4; ++r)
#pragma unroll
        for (int j = 0; j < 8; ++j) hv[r][j] = g_h[(row0 + r) * 256 + lane + 32 * j];

    float lg[4][10];
#pragma unroll
    for (int o = 0; o < 10; ++o) {
        const float* w = W2 + o * 256;
        float wv[8];
#pragma unroll
        for (int j = 0; j < 8; ++j) wv[j] = __ldg(w + lane + 32 * j);
        float p[4] = {0.f, 0.f, 0.f, 0.f};
#pragma unroll
        for (int j = 0; j < 8; ++j)
#pragma unroll
            for (int r = 0; r < 4; ++r) p[r] += hv[r][j] * wv[j];
#pragma unroll
        for (int off = 16; off > 0; off >>= 1)
#pragma unroll
            for (int r = 0; r < 4; ++r) p[r] += __shfl_xor_sync(0xffffffffu, p[r], off);
        float bo = __ldg(b2 + o);
#pragma unroll
        for (int r = 0; r < 4; ++r) lg[r][o] = p[r] + bo;
    }

#pragma unroll
    for (int r = 0; r < 4; ++r) {
        float m = lg[r][0];
#pragma unroll
        for (int o = 1; o < 10; ++o) m = fmaxf(m, lg[r][o]);
        float sum = 0.f;
#pragma unroll
        for (int o = 0; o < 10; ++o) sum += expf(lg[r][o] - m);
        float lse = m + logf(sum);
        float myv = 0.f;
#pragma unroll
        for (int o = 0; o < 10; ++o)
            if (lane == o) myv = lg[r][o];
        if (lane < 10) out[(row0 + r) * 10 + lane] = myv - lse;
    }
}

// ---------------------------------------------------------------------------
extern "C" void kernel_launch(void* const* d_in, const int* in_sizes, int n_in,
                              void* d_out, int out_size) {
    const float* x   = (const float*)d_in[0];
    const float* var = (const float*)d_in[1];
    const float* W1  = (const float*)d_in[2];
    const float* b1  = (const float*)d_in[3];
    const float* W2  = (const float*)d_in[4];
    const float* b2  = (const float*)d_in[5];
    float* out = (float*)d_out;

    int B = in_sizes[0] / 784;

    var_precompute_kernel<<<1, 8>>>(var);
    convert_w1_kernel<<<(256 * 196 + 255) / 256, 256>>>(W1);

    int np = B * 196;
    quanv_kernel<<<(np + 255) / 256, 256>>>(x, B);

    dim3 g1(B / 128, 256 / 64);
    gemm1_kernel<<<g1, 256>>>(b1);

    // 8 warps/block, 4 rows/warp -> 32 rows per block
    int head_blocks = (B / 4 + 7) / 8;
    head_kernel<<<head_blocks, 256>>>(W2, b2, out, B);
}

// round 10
// speedup vs baseline: 2.9623x; 1.4611x over previous
#include <cuda_runtime.h>
#include <cuda_fp16.h>
#include <math.h>

#define BMAX 4096
#define KP 832           // 784 padded to 13*64

// scratch (no allocations allowed)
__device__ __half g_A[BMAX * KP];     // feats fp16, padded
__device__ __half g_B[256 * KP];      // W1 fp16, padded
__device__ float g_h[BMAX * 256];

__device__ __forceinline__ unsigned pack_half2(__half a, __half b) {
    __half2 t = __halves2half2(a, b);
    return *(unsigned*)&t;
}

// ---------------------------------------------------------------------------
// Convert W1 [256][784] fp32 -> g_B fp16 [256][832]. Each thread: 4 k's.
// ---------------------------------------------------------------------------
__global__ __launch_bounds__(256) void convert_w1_kernel(const float* __restrict__ W1) {
    int t = blockIdx.x * 256 + threadIdx.x;
    if (t >= 256 * 196) return;
    int n = t / 196;
    int kq = t - n * 196;
    int k = kq * 4;

    float4 w = *(const float4*)(W1 + n * 784 + k);
    uint2 hp;
    hp.x = pack_half2(__float2half_rn(w.x), __float2half_rn(w.y));
    hp.y = pack_half2(__float2half_rn(w.z), __float2half_rn(w.w));

    __half* row = g_B + n * KP;
    *(uint2*)(row + k) = hp;
    if (kq < 12) {
        *(uint2*)(row + 784 + kq * 4) = make_uint2(0u, 0u);  // pad 784..831
    }
}

// ---------------------------------------------------------------------------
// Quanvolution. Depth-0 variational RY folds into the encoder (product state
// is separable): angle_w = pixel_w + var[0][w]. CNOT rings are register
// permutations (free after unrolling). One full RY layer (depth 1) remains.
// ---------------------------------------------------------------------------
__global__ void quanv_kernel(const float* __restrict__ x,
                             const float* __restrict__ var, int B) {
    int idx = blockIdx.x * blockDim.x + threadIdx.x;
    if (idx >= B * 196) return;
    int b = idx / 196;
    int p = idx - b * 196;
    int r = p / 14;
    int c = p - r * 14;

    const float* img = x + b * 784;
    float2 top = *(const float2*)(img + (2 * r) * 28 + 2 * c);
    float2 bot = *(const float2*)(img + (2 * r + 1) * 28 + 2 * c);

    // encoder + depth-0 RY folded
    float ang[4];
    ang[0] = top.x + __ldg(var + 0);
    ang[1] = top.y + __ldg(var + 1);
    ang[2] = bot.x + __ldg(var + 2);
    ang[3] = bot.y + __ldg(var + 3);

    float ec[4], es[4];
#pragma unroll
    for (int w = 0; w < 4; ++w) __sincosf(0.5f * ang[w], &es[w], &ec[w]);

    // depth-1 fixed rotations
    float vc[4], vs[4];
#pragma unroll
    for (int w = 0; w < 4; ++w) __sincosf(0.5f * __ldg(var + 4 + w), &vs[w], &vc[w]);

    // product state via 2-level factoring: i bits (w0,w1,w2,w3) = (b3,b2,b1,b0)
    float A01[4], A23[4];
    A01[0] = ec[0] * ec[1]; A01[1] = ec[0] * es[1];
    A01[2] = es[0] * ec[1]; A01[3] = es[0] * es[1];
    A23[0] = ec[2] * ec[3]; A23[1] = ec[2] * es[3];
    A23[2] = es[2] * ec[3]; A23[3] = es[2] * es[3];

    float st[16];
#pragma unroll
    for (int i = 0; i < 16; ++i) st[i] = A01[i >> 2] * A23[i & 3];

    // CNOT ring (register permutation)
#pragma unroll
    for (int cw = 0; cw < 4; ++cw) {
        int tw = (cw + 1) & 3;
        int cm = 8 >> cw, tm = 8 >> tw;
#pragma unroll
        for (int i = 0; i < 16; ++i) {
            if ((i & cm) && !(i & tm)) {
                int j = i | tm;
                float t = st[i]; st[i] = st[j]; st[j] = t;
            }
        }
    }

    // depth-1 RY layer (full 16-amplitude rotations)
#pragma unroll
    for (int w = 0; w < 4; ++w) {
        float cc = vc[w], ss = vs[w];
        int mask = 8 >> w;
#pragma unroll
        for (int i = 0; i < 16; ++i) {
            if (!(i & mask)) {
                int j = i | mask;
                float a = st[i], bb = st[j];
                st[i] = cc * a - ss * bb;
                st[j] = ss * a + cc * bb;
            }
        }
    }

    // CNOT ring (register permutation)
#pragma unroll
    for (int cw = 0; cw < 4; ++cw) {
        int tw = (cw + 1) & 3;
        int cm = 8 >> cw, tm = 8 >> tw;
#pragma unroll
        for (int i = 0; i < 16; ++i) {
            if ((i & cm) && !(i & tm)) {
                int j = i | tm;
                float t = st[i]; st[i] = st[j]; st[j] = t;
            }
        }
    }

    float q[16];
#pragma unroll
    for (int i = 0; i < 16; ++i) q[i] = st[i] * st[i];

    float fo[4];
#pragma unroll
    for (int w = 0; w < 4; ++w) {
        int m = 8 >> w;
        float acc = 0.f;
#pragma unroll
        for (int i = 0; i < 16; ++i) acc += (i & m) ? -q[i] : q[i];
        fo[w] = acc;
    }

    uint2 hp;
    hp.x = pack_half2(__float2half_rn(fo[0]), __float2half_rn(fo[1]));
    hp.y = pack_half2(__float2half_rn(fo[2]), __float2half_rn(fo[3]));

    __half* row = g_A + (size_t)b * KP;
    *(uint2*)(row + p * 4) = hp;
    if (p < 12) {
        *(uint2*)(row + 784 + p * 4) = make_uint2(0u, 0u);  // pad 784..831
    }
}

// ---------------------------------------------------------------------------
// Tensor-core GEMM1: h = relu(A @ B^T + b1).  M=B, N=256, K=832 (fp16).
// BM=64, BN=64, BK=64, 4 warps (2x2), warp tile 32x32 via m16n8k16 mma.
// 3-stage cp.async pipeline, one __syncthreads per iter, grid 256 CTAs.
// ---------------------------------------------------------------------------
#define GBK 64
#define NITER (KP / GBK)   // 13
#define ASTRIDE 72         // 144B row stride, ldmatrix conflict-free

__device__ __forceinline__ void mma_f16(float* c, const unsigned* a, const unsigned* b) {
    asm volatile(
        "mma.sync.aligned.m16n8k16.row.col.f32.f16.f16.f32 "
        "{%0,%1,%2,%3}, {%4,%5,%6,%7}, {%8,%9}, {%0,%1,%2,%3};\n"
        : "+f"(c[0]), "+f"(c[1]), "+f"(c[2]), "+f"(c[3])
        : "r"(a[0]), "r"(a[1]), "r"(a[2]), "r"(a[3]), "r"(b[0]), "r"(b[1]));
}

__global__ __launch_bounds__(128, 3) void gemm1_kernel(const float* __restrict__ b1) {
    __shared__ __half As[3][64][ASTRIDE];   // 27.6 KB
    __shared__ __half Bs[3][64][ASTRIDE];   // 27.6 KB (total 55.3 KB)

    int tid = threadIdx.x;
    int wid = tid >> 5;
    int lane = tid & 31;
    int warp_m = wid & 1;      // 0..1 -> m offset 32*warp_m
    int warp_n = wid >> 1;     // 0..1 -> n offset 32*warp_n
    int bm = blockIdx.x * 64;
    int bn = blockIdx.y * 64;

    float acc[2][4][4];
#pragma unroll
    for (int i = 0; i < 2; ++i)
#pragma unroll
        for (int j = 0; j < 4; ++j)
#pragma unroll
            for (int k = 0; k < 4; ++k) acc[i][j][k] = 0.f;

#define CPA(dst, src) asm volatile("cp.async.cg.shared.global [%0], [%1], 16;\n" ::"r"(dst), "l"(src))
#define LOAD_STAGE(IT, BUF)                                                      \
    do {                                                                         \
        int k0 = (IT) * GBK;                                                     \
        _Pragma("unroll")                                                        \
        for (int i_ = 0; i_ < 4; ++i_) {                                         \
            int id_ = tid + i_ * 128;                                            \
            int row_ = id_ >> 3, cc_ = id_ & 7;                                  \
            CPA((unsigned)__cvta_generic_to_shared(&As[BUF][row_][cc_ * 8]),     \
                g_A + (size_t)(bm + row_) * KP + k0 + cc_ * 8);                  \
            CPA((unsigned)__cvta_generic_to_shared(&Bs[BUF][row_][cc_ * 8]),     \
                g_B + (size_t)(bn + row_) * KP + k0 + cc_ * 8);                  \
        }                                                                        \
    } while (0)

    LOAD_STAGE(0, 0);
    asm volatile("cp.async.commit_group;\n" ::);
    LOAD_STAGE(1, 1);
    asm volatile("cp.async.commit_group;\n" ::);

    int gid = lane >> 3;   // ldmatrix address group
    int wi = lane & 7;

    for (int it = 0; it < NITER; ++it) {
        int buf = it % 3;
        asm volatile("cp.async.wait_group 1;\n" ::);
        __syncthreads();   // stage `buf` ready; compute of it-1 fully retired

        if (it + 2 < NITER) LOAD_STAGE(it + 2, (it + 2) % 3);
        asm volatile("cp.async.commit_group;\n" ::);

#pragma unroll
        for (int kk = 0; kk < 4; ++kk) {
            unsigned a[2][4];
#pragma unroll
            for (int mf = 0; mf < 2; ++mf) {
                int row = warp_m * 32 + mf * 16 + (gid & 1) * 8 + wi;
                int col = kk * 16 + (gid >> 1) * 8;
                unsigned addr = (unsigned)__cvta_generic_to_shared(&As[buf][row][col]);
                asm volatile(
                    "ldmatrix.sync.aligned.m8n8.x4.shared.b16 {%0,%1,%2,%3}, [%4];\n"
                    : "=r"(a[mf][0]), "=r"(a[mf][1]), "=r"(a[mf][2]), "=r"(a[mf][3])
                    : "r"(addr));
            }
            unsigned b[4][2];
#pragma unroll
            for (int nh = 0; nh < 2; ++nh) {
                int row = warp_n * 32 + nh * 16 + (gid >> 1) * 8 + wi;
                int col = kk * 16 + (gid & 1) * 8;
                unsigned addr = (unsigned)__cvta_generic_to_shared(&Bs[buf][row][col]);
                asm volatile(
                    "ldmatrix.sync.aligned.m8n8.x4.shared.b16 {%0,%1,%2,%3}, [%4];\n"
                    : "=r"(b[2 * nh][0]), "=r"(b[2 * nh][1]),
                      "=r"(b[2 * nh + 1][0]), "=r"(b[2 * nh + 1][1])
                    : "r"(addr));
            }
#pragma unroll
            for (int mf = 0; mf < 2; ++mf)
#pragma unroll
                for (int nf = 0; nf < 4; ++nf) mma_f16(acc[mf][nf], a[mf], b[nf]);
        }
    }

    // epilogue: bias + relu, fp32 out
#pragma unroll
    for (int nf = 0; nf < 4; ++nf) {
        int n = bn + warp_n * 32 + nf * 8 + (lane & 3) * 2;
        float2 bias = *(const float2*)(b1 + n);
#pragma unroll
        for (int mf = 0; mf < 2; ++mf) {
            int m = bm + warp_m * 32 + mf * 16 + (lane >> 2);
            float2 o0, o1;
            o0.x = fmaxf(acc[mf][nf][0] + bias.x, 0.f);
            o0.y = fmaxf(acc[mf][nf][1] + bias.y, 0.f);
            o1.x = fmaxf(acc[mf][nf][2] + bias.x, 0.f);
            o1.y = fmaxf(acc[mf][nf][3] + bias.y, 0.f);
            *(float2*)(g_h + m * 256 + n) = o0;
            *(float2*)(g_h + (m + 8) * 256 + n) = o1;
        }
    }
#undef LOAD_STAGE
#undef CPA
}

// ---------------------------------------------------------------------------
// Head: logits = h @ W2^T + b2, then log_softmax. 4 rows per warp.
// ---------------------------------------------------------------------------
__global__ __launch_bounds__(256) void head_kernel(const float* __restrict__ W2,
                                                   const float* __restrict__ b2,
                                                   float* __restrict__ out, int B) {
    int warp = threadIdx.x >> 5;
    int lane = threadIdx.x & 31;
    int row0 = (blockIdx.x * 8 + warp) * 4;
    if (row0 >= B) return;

    float hv[4][8];
#pragma unroll
    for (int r = 0; r < 4; ++r)
#pragma unroll
        for (int j = 0; j < 8; ++j) hv[r][j] = g_h[(row0 + r) * 256 + lane + 32 * j];

    float lg[4][10];
#pragma unroll
    for (int o = 0; o < 10; ++o) {
        const float* w = W2 + o * 256;
        float wv[8];
#pragma unroll
        for (int j = 0; j < 8; ++j) wv[j] = __ldg(w + lane + 32 * j);
        float p[4] = {0.f, 0.f, 0.f, 0.f};
#pragma unroll
        for (int j = 0; j < 8; ++j)
#pragma unroll
            for (int r = 0; r < 4; ++r) p[r] += hv[r][j] * wv[j];
#pragma unroll
        for (int off = 16; off > 0; off >>= 1)
#pragma unroll
            for (int r = 0; r < 4; ++r) p[r] += __shfl_xor_sync(0xffffffffu, p[r], off);
        float bo = __ldg(b2 + o);
#pragma unroll
        for (int r = 0; r < 4; ++r) lg[r][o] = p[r] + bo;
    }

#pragma unroll
    for (int r = 0; r < 4; ++r) {
        float m = lg[r][0];
#pragma unroll
        for (int o = 1; o < 10; ++o) m = fmaxf(m, lg[r][o]);
        float sum = 0.f;
#pragma unroll
        for (int o = 0; o < 10; ++o) sum += expf(lg[r][o] - m);
        float lse = m + logf(sum);
        float myv = 0.f;
#pragma unroll
        for (int o = 0; o < 10; ++o)
            if (lane == o) myv = lg[r][o];
        if (lane < 10) out[(row0 + r) * 10 + lane] = myv - lse;
    }
}

// ---------------------------------------------------------------------------
extern "C" void kernel_launch(void* const* d_in, const int* in_sizes, int n_in,
                              void* d_out, int out_size) {
    const float* x   = (const float*)d_in[0];
    const float* var = (const float*)d_in[1];
    const float* W1  = (const float*)d_in[2];
    const float* b1  = (const float*)d_in[3];
    const float* W2  = (const float*)d_in[4];
    const float* b2  = (const float*)d_in[5];
    float* out = (float*)d_out;

    int B = in_sizes[0] / 784;

    convert_w1_kernel<<<(256 * 196 + 255) / 256, 256>>>(W1);

    int np = B * 196;
    quanv_kernel<<<(np + 255) / 256, 256>>>(x, var, B);

    dim3 g1(B / 64, 256 / 64);
    gemm1_kernel<<<g1, 128>>>(b1);

    // 8 warps/block, 4 rows/warp -> 32 rows per block
    int head_blocks = (B / 4 + 7) / 8;
    head_kernel<<<head_blocks, 256>>>(W2, b2, out, B);
}

// round 11
// speedup vs baseline: 2.9658x; 1.0012x over previous
#include <cuda_runtime.h>
#include <cuda_fp16.h>
#include <math.h>

#define BMAX 4096
#define KP 832           // 784 padded to 13*64

// scratch (no allocations allowed)
__device__ __half g_A[BMAX * KP];     // feats fp16, padded
__device__ __half g_B[256 * KP];      // W1 fp16, padded
__device__ float g_h[BMAX * 256];

__device__ __forceinline__ unsigned pack_half2(__half a, __half b) {
    __half2 t = __halves2half2(a, b);
    return *(unsigned*)&t;
}

// ---------------------------------------------------------------------------
// Convert W1 [256][784] fp32 -> g_B fp16 [256][832]. Each thread: 4 k's.
// ---------------------------------------------------------------------------
__global__ __launch_bounds__(256) void convert_w1_kernel(const float* __restrict__ W1) {
    int t = blockIdx.x * 256 + threadIdx.x;
    if (t >= 256 * 196) return;
    int n = t / 196;
    int kq = t - n * 196;
    int k = kq * 4;

    float4 w = *(const float4*)(W1 + n * 784 + k);
    uint2 hp;
    hp.x = pack_half2(__float2half_rn(w.x), __float2half_rn(w.y));
    hp.y = pack_half2(__float2half_rn(w.z), __float2half_rn(w.w));

    __half* row = g_B + n * KP;
    *(uint2*)(row + k) = hp;
    if (kq < 12) {
        *(uint2*)(row + 784 + kq * 4) = make_uint2(0u, 0u);  // pad 784..831
    }
}

// ---------------------------------------------------------------------------
// Quanvolution. Depth-0 variational RY folds into the encoder (product state
// is separable): angle_w = pixel_w + var[0][w]. CNOT rings are register
// permutations (free after unrolling). One full RY layer (depth 1) remains.
// ---------------------------------------------------------------------------
__global__ void quanv_kernel(const float* __restrict__ x,
                             const float* __restrict__ var, int B) {
    int idx = blockIdx.x * blockDim.x + threadIdx.x;
    if (idx >= B * 196) return;
    int b = idx / 196;
    int p = idx - b * 196;
    int r = p / 14;
    int c = p - r * 14;

    const float* img = x + b * 784;
    float2 top = *(const float2*)(img + (2 * r) * 28 + 2 * c);
    float2 bot = *(const float2*)(img + (2 * r + 1) * 28 + 2 * c);

    // encoder + depth-0 RY folded
    float ang[4];
    ang[0] = top.x + __ldg(var + 0);
    ang[1] = top.y + __ldg(var + 1);
    ang[2] = bot.x + __ldg(var + 2);
    ang[3] = bot.y + __ldg(var + 3);

    float ec[4], es[4];
#pragma unroll
    for (int w = 0; w < 4; ++w) __sincosf(0.5f * ang[w], &es[w], &ec[w]);

    // depth-1 fixed rotations
    float vc[4], vs[4];
#pragma unroll
    for (int w = 0; w < 4; ++w) __sincosf(0.5f * __ldg(var + 4 + w), &vs[w], &vc[w]);

    // product state via 2-level factoring: i bits (w0,w1,w2,w3) = (b3,b2,b1,b0)
    float A01[4], A23[4];
    A01[0] = ec[0] * ec[1]; A01[1] = ec[0] * es[1];
    A01[2] = es[0] * ec[1]; A01[3] = es[0] * es[1];
    A23[0] = ec[2] * ec[3]; A23[1] = ec[2] * es[3];
    A23[2] = es[2] * ec[3]; A23[3] = es[2] * es[3];

    float st[16];
#pragma unroll
    for (int i = 0; i < 16; ++i) st[i] = A01[i >> 2] * A23[i & 3];

    // CNOT ring (register permutation)
#pragma unroll
    for (int cw = 0; cw < 4; ++cw) {
        int tw = (cw + 1) & 3;
        int cm = 8 >> cw, tm = 8 >> tw;
#pragma unroll
        for (int i = 0; i < 16; ++i) {
            if ((i & cm) && !(i & tm)) {
                int j = i | tm;
                float t = st[i]; st[i] = st[j]; st[j] = t;
            }
        }
    }

    // depth-1 RY layer (full 16-amplitude rotations)
#pragma unroll
    for (int w = 0; w < 4; ++w) {
        float cc = vc[w], ss = vs[w];
        int mask = 8 >> w;
#pragma unroll
        for (int i = 0; i < 16; ++i) {
            if (!(i & mask)) {
                int j = i | mask;
                float a = st[i], bb = st[j];
                st[i] = cc * a - ss * bb;
                st[j] = ss * a + cc * bb;
            }
        }
    }

    // CNOT ring (register permutation)
#pragma unroll
    for (int cw = 0; cw < 4; ++cw) {
        int tw = (cw + 1) & 3;
        int cm = 8 >> cw, tm = 8 >> tw;
#pragma unroll
        for (int i = 0; i < 16; ++i) {
            if ((i & cm) && !(i & tm)) {
                int j = i | tm;
                float t = st[i]; st[i] = st[j]; st[j] = t;
            }
        }
    }

    float q[16];
#pragma unroll
    for (int i = 0; i < 16; ++i) q[i] = st[i] * st[i];

    float fo[4];
#pragma unroll
    for (int w = 0; w < 4; ++w) {
        int m = 8 >> w;
        float acc = 0.f;
#pragma unroll
        for (int i = 0; i < 16; ++i) acc += (i & m) ? -q[i] : q[i];
        fo[w] = acc;
    }

    uint2 hp;
    hp.x = pack_half2(__float2half_rn(fo[0]), __float2half_rn(fo[1]));
    hp.y = pack_half2(__float2half_rn(fo[2]), __float2half_rn(fo[3]));

    __half* row = g_A + (size_t)b * KP;
    *(uint2*)(row + p * 4) = hp;
    if (p < 12) {
        *(uint2*)(row + 784 + p * 4) = make_uint2(0u, 0u);  // pad 784..831
    }
}

// ---------------------------------------------------------------------------
// Tensor-core GEMM1: h = relu(A @ B^T + b1).  M=B, N=256, K=832 (fp16).
// BM=64, BN=64, BK=64, 4 warps (2x2), warp tile 32x32 via m16n8k16 mma.
// 3-stage cp.async pipeline, one __syncthreads per iter, grid 256 CTAs.
// ---------------------------------------------------------------------------
#define GBK 64
#define NITER (KP / GBK)   // 13
#define ASTRIDE 72         // 144B row stride, ldmatrix conflict-free

__device__ __forceinline__ void mma_f16(float* c, const unsigned* a, const unsigned* b) {
    asm volatile(
        "mma.sync.aligned.m16n8k16.row.col.f32.f16.f16.f32 "
        "{%0,%1,%2,%3}, {%4,%5,%6,%7}, {%8,%9}, {%0,%1,%2,%3};\n"
        : "+f"(c[0]), "+f"(c[1]), "+f"(c[2]), "+f"(c[3])
        : "r"(a[0]), "r"(a[1]), "r"(a[2]), "r"(a[3]), "r"(b[0]), "r"(b[1]));
}

__global__ __launch_bounds__(128, 3) void gemm1_kernel(const float* __restrict__ b1) {
    __shared__ __half As[3][64][ASTRIDE];   // 27.6 KB
    __shared__ __half Bs[3][64][ASTRIDE];   // 27.6 KB (total 55.3 KB)

    int tid = threadIdx.x;
    int wid = tid >> 5;
    int lane = tid & 31;
    int warp_m = wid & 1;      // 0..1 -> m offset 32*warp_m
    int warp_n = wid >> 1;     // 0..1 -> n offset 32*warp_n
    int bm = blockIdx.x * 64;
    int bn = blockIdx.y * 64;

    float acc[2][4][4];
#pragma unroll
    for (int i = 0; i < 2; ++i)
#pragma unroll
        for (int j = 0; j < 4; ++j)
#pragma unroll
            for (int k = 0; k < 4; ++k) acc[i][j][k] = 0.f;

#define CPA(dst, src) asm volatile("cp.async.cg.shared.global [%0], [%1], 16;\n" ::"r"(dst), "l"(src))
#define LOAD_STAGE(IT, BUF)                                                      \
    do {                                                                         \
        int k0 = (IT) * GBK;                                                     \
        _Pragma("unroll")                                                        \
        for (int i_ = 0; i_ < 4; ++i_) {                                         \
            int id_ = tid + i_ * 128;                                            \
            int row_ = id_ >> 3, cc_ = id_ & 7;                                  \
            CPA((unsigned)__cvta_generic_to_shared(&As[BUF][row_][cc_ * 8]),     \
                g_A + (size_t)(bm + row_) * KP + k0 + cc_ * 8);                  \
            CPA((unsigned)__cvta_generic_to_shared(&Bs[BUF][row_][cc_ * 8]),     \
                g_B + (size_t)(bn + row_) * KP + k0 + cc_ * 8);                  \
        }                                                                        \
    } while (0)

    LOAD_STAGE(0, 0);
    asm volatile("cp.async.commit_group;\n" ::);
    LOAD_STAGE(1, 1);
    asm volatile("cp.async.commit_group;\n" ::);

    int gid = lane >> 3;   // ldmatrix address group
    int wi = lane & 7;

    for (int it = 0; it < NITER; ++it) {
        int buf = it % 3;
        asm volatile("cp.async.wait_group 1;\n" ::);
        __syncthreads();   // stage `buf` ready; compute of it-1 fully retired

        if (it + 2 < NITER) LOAD_STAGE(it + 2, (it + 2) % 3);
        asm volatile("cp.async.commit_group;\n" ::);

#pragma unroll
        for (int kk = 0; kk < 4; ++kk) {
            unsigned a[2][4];
#pragma unroll
            for (int mf = 0; mf < 2; ++mf) {
                int row = warp_m * 32 + mf * 16 + (gid & 1) * 8 + wi;
                int col = kk * 16 + (gid >> 1) * 8;
                unsigned addr = (unsigned)__cvta_generic_to_shared(&As[buf][row][col]);
                asm volatile(
                    "ldmatrix.sync.aligned.m8n8.x4.shared.b16 {%0,%1,%2,%3}, [%4];\n"
                    : "=r"(a[mf][0]), "=r"(a[mf][1]), "=r"(a[mf][2]), "=r"(a[mf][3])
                    : "r"(addr));
            }
            unsigned b[4][2];
#pragma unroll
            for (int nh = 0; nh < 2; ++nh) {
                int row = warp_n * 32 + nh * 16 + (gid >> 1) * 8 + wi;
                int col = kk * 16 + (gid & 1) * 8;
                unsigned addr = (unsigned)__cvta_generic_to_shared(&Bs[buf][row][col]);
                asm volatile(
                    "ldmatrix.sync.aligned.m8n8.x4.shared.b16 {%0,%1,%2,%3}, [%4];\n"
                    : "=r"(b[2 * nh][0]), "=r"(b[2 * nh][1]),
                      "=r"(b[2 * nh + 1][0]), "=r"(b[2 * nh + 1][1])
                    : "r"(addr));
            }
#pragma unroll
            for (int mf = 0; mf < 2; ++mf)
#pragma unroll
                for (int nf = 0; nf < 4; ++nf) mma_f16(acc[mf][nf], a[mf], b[nf]);
        }
    }

    // epilogue: bias + relu, fp32 out
#pragma unroll
    for (int nf = 0; nf < 4; ++nf) {
        int n = bn + warp_n * 32 + nf * 8 + (lane & 3) * 2;
        float2 bias = *(const float2*)(b1 + n);
#pragma unroll
        for (int mf = 0; mf < 2; ++mf) {
            int m = bm + warp_m * 32 + mf * 16 + (lane >> 2);
            float2 o0, o1;
            o0.x = fmaxf(acc[mf][nf][0] + bias.x, 0.f);
            o0.y = fmaxf(acc[mf][nf][1] + bias.y, 0.f);
            o1.x = fmaxf(acc[mf][nf][2] + bias.x, 0.f);
            o1.y = fmaxf(acc[mf][nf][3] + bias.y, 0.f);
            *(float2*)(g_h + m * 256 + n) = o0;
            *(float2*)(g_h + (m + 8) * 256 + n) = o1;
        }
    }
#undef LOAD_STAGE
#undef CPA
}

// ---------------------------------------------------------------------------
// Head: logits = h @ W2^T + b2, then log_softmax. 4 rows per warp.
// ---------------------------------------------------------------------------
__global__ __launch_bounds__(256) void head_kernel(const float* __restrict__ W2,
                                                   const float* __restrict__ b2,
                                                   float* __restrict__ out, int B) {
    int warp = threadIdx.x >> 5;
    int lane = threadIdx.x & 31;
    int row0 = (blockIdx.x * 8 + warp) * 4;
    if (row0 >= B) return;

    float hv[4][8];
#pragma unroll
    for (int r = 0; r < 4; ++r)
#pragma unroll
        for (int j = 0; j < 8; ++j) hv[r][j] = g_h[(row0 + r) * 256 + lane + 32 * j];

    float lg[4][10];
#pragma unroll
    for (int o = 0; o < 10; ++o) {
        const float* w = W2 + o * 256;
        float wv[8];
#pragma unroll
        for (int j = 0; j < 8; ++j) wv[j] = __ldg(w + lane + 32 * j);
        float p[4] = {0.f, 0.f, 0.f, 0.f};
#pragma unroll
        for (int j = 0; j < 8; ++j)
#pragma unroll
            for (int r = 0; r < 4; ++r) p[r] += hv[r][j] * wv[j];
#pragma unroll
        for (int off = 16; off > 0; off >>= 1)
#pragma unroll
            for (int r = 0; r < 4; ++r) p[r] += __shfl_xor_sync(0xffffffffu, p[r], off);
        float bo = __ldg(b2 + o);
#pragma unroll
        for (int r = 0; r < 4; ++r) lg[r][o] = p[r] + bo;
    }

#pragma unroll
    for (int r = 0; r < 4; ++r) {
        float m = lg[r][0];
#pragma unroll
        for (int o = 1; o < 10; ++o) m = fmaxf(m, lg[r][o]);
        float sum = 0.f;
#pragma unroll
        for (int o = 0; o < 10; ++o) sum += expf(lg[r][o] - m);
        float lse = m + logf(sum);
        float myv = 0.f;
#pragma unroll
        for (int o = 0; o < 10; ++o)
            if (lane == o) myv = lg[r][o];
        if (lane < 10) out[(row0 + r) * 10 + lane] = myv - lse;
    }
}

// ---------------------------------------------------------------------------
extern "C" void kernel_launch(void* const* d_in, const int* in_sizes, int n_in,
                              void* d_out, int out_size) {
    const float* x   = (const float*)d_in[0];
    const float* var = (const float*)d_in[1];
    const float* W1  = (const float*)d_in[2];
    const float* b1  = (const float*)d_in[3];
    const float* W2  = (const float*)d_in[4];
    const float* b2  = (const float*)d_in[5];
    float* out = (float*)d_out;

    int B = in_sizes[0] / 784;

    convert_w1_kernel<<<(256 * 196 + 255) / 256, 256>>>(W1);

    int np = B * 196;
    quanv_kernel<<<(np + 255) / 256, 256>>>(x, var, B);

    dim3 g1(B / 64, 256 / 64);
    gemm1_kernel<<<g1, 128>>>(b1);

    // 8 warps/block, 4 rows/warp -> 32 rows per block
    int head_blocks = (B / 4 + 7) / 8;
    head_kernel<<<head_blocks, 256>>>(W2, b2, out, B);
}

// round 12
// speedup vs baseline: 3.0048x; 1.0132x over previous
#include <cuda_runtime.h>
#include <cuda_fp16.h>
#include <math.h>

#define BMAX 4096
#define KP 832           // 784 padded to 13*64
#define LPW 12           // padded logit-partial row width (10 -> 12)

// scratch (no allocations allowed)
__device__ __half g_A[BMAX * KP];            // feats fp16, padded
__device__ __half g_B[256 * KP];             // W1 fp16, padded
__device__ float g_lpart[8 * BMAX * LPW];    // per-slice partial logits

__device__ __forceinline__ unsigned pack_half2(__half a, __half b) {
    __half2 t = __halves2half2(a, b);
    return *(unsigned*)&t;
}

// ---------------------------------------------------------------------------
// Convert W1 [256][784] fp32 -> g_B fp16 [256][832]. Each thread: 4 k's.
// ---------------------------------------------------------------------------
__global__ __launch_bounds__(256) void convert_w1_kernel(const float* __restrict__ W1) {
    int t = blockIdx.x * 256 + threadIdx.x;
    if (t >= 256 * 196) return;
    int n = t / 196;
    int kq = t - n * 196;
    int k = kq * 4;

    float4 w = *(const float4*)(W1 + n * 784 + k);
    uint2 hp;
    hp.x = pack_half2(__float2half_rn(w.x), __float2half_rn(w.y));
    hp.y = pack_half2(__float2half_rn(w.z), __float2half_rn(w.w));

    __half* row = g_B + n * KP;
    *(uint2*)(row + k) = hp;
    if (kq < 12) {
        *(uint2*)(row + 784 + kq * 4) = make_uint2(0u, 0u);  // pad 784..831
    }
}

// ---------------------------------------------------------------------------
// Quanvolution. Depth-0 variational RY folds into the encoder; CNOT rings are
// register permutations. One full RY layer (depth 1) remains.
// ---------------------------------------------------------------------------
__global__ void quanv_kernel(const float* __restrict__ x,
                             const float* __restrict__ var, int B) {
    int idx = blockIdx.x * blockDim.x + threadIdx.x;
    if (idx >= B * 196) return;
    int b = idx / 196;
    int p = idx - b * 196;
    int r = p / 14;
    int c = p - r * 14;

    const float* img = x + b * 784;
    float2 top = *(const float2*)(img + (2 * r) * 28 + 2 * c);
    float2 bot = *(const float2*)(img + (2 * r + 1) * 28 + 2 * c);

    float ang[4];
    ang[0] = top.x + __ldg(var + 0);
    ang[1] = top.y + __ldg(var + 1);
    ang[2] = bot.x + __ldg(var + 2);
    ang[3] = bot.y + __ldg(var + 3);

    float ec[4], es[4];
#pragma unroll
    for (int w = 0; w < 4; ++w) __sincosf(0.5f * ang[w], &es[w], &ec[w]);

    float vc[4], vs[4];
#pragma unroll
    for (int w = 0; w < 4; ++w) __sincosf(0.5f * __ldg(var + 4 + w), &vs[w], &vc[w]);

    float A01[4], A23[4];
    A01[0] = ec[0] * ec[1]; A01[1] = ec[0] * es[1];
    A01[2] = es[0] * ec[1]; A01[3] = es[0] * es[1];
    A23[0] = ec[2] * ec[3]; A23[1] = ec[2] * es[3];
    A23[2] = es[2] * ec[3]; A23[3] = es[2] * es[3];

    float st[16];
#pragma unroll
    for (int i = 0; i < 16; ++i) st[i] = A01[i >> 2] * A23[i & 3];

#pragma unroll
    for (int cw = 0; cw < 4; ++cw) {
        int tw = (cw + 1) & 3;
        int cm = 8 >> cw, tm = 8 >> tw;
#pragma unroll
        for (int i = 0; i < 16; ++i) {
            if ((i & cm) && !(i & tm)) {
                int j = i | tm;
                float t = st[i]; st[i] = st[j]; st[j] = t;
            }
        }
    }

#pragma unroll
    for (int w = 0; w < 4; ++w) {
        float cc = vc[w], ss = vs[w];
        int mask = 8 >> w;
#pragma unroll
        for (int i = 0; i < 16; ++i) {
            if (!(i & mask)) {
                int j = i | mask;
                float a = st[i], bb = st[j];
                st[i] = cc * a - ss * bb;
                st[j] = ss * a + cc * bb;
            }
        }
    }

#pragma unroll
    for (int cw = 0; cw < 4; ++cw) {
        int tw = (cw + 1) & 3;
        int cm = 8 >> cw, tm = 8 >> tw;
#pragma unroll
        for (int i = 0; i < 16; ++i) {
            if ((i & cm) && !(i & tm)) {
                int j = i | tm;
                float t = st[i]; st[i] = st[j]; st[j] = t;
            }
        }
    }

    float q[16];
#pragma unroll
    for (int i = 0; i < 16; ++i) q[i] = st[i] * st[i];

    float fo[4];
#pragma unroll
    for (int w = 0; w < 4; ++w) {
        int m = 8 >> w;
        float acc = 0.f;
#pragma unroll
        for (int i = 0; i < 16; ++i) acc += (i & m) ? -q[i] : q[i];
        fo[w] = acc;
    }

    uint2 hp;
    hp.x = pack_half2(__float2half_rn(fo[0]), __float2half_rn(fo[1]));
    hp.y = pack_half2(__float2half_rn(fo[2]), __float2half_rn(fo[3]));

    __half* row = g_A + (size_t)b * KP;
    *(uint2*)(row + p * 4) = hp;
    if (p < 12) {
        *(uint2*)(row + 784 + p * 4) = make_uint2(0u, 0u);  // pad 784..831
    }
}

// ---------------------------------------------------------------------------
// Tensor-core GEMM1 + fused logit partials.
// h = relu(A @ B^T + b1); lpart[slice][m][o] = sum_{n in slice} h[m][n]*W2[o][n]
// BM=64, BN=64, BK=64, 4 warps (2x2), warp tile 32x32 via m16n8k16 mma.
// 3-stage cp.async pipeline, one __syncthreads per iter, grid (B/64, 4).
// ---------------------------------------------------------------------------
#define GBK 64
#define NITER (KP / GBK)   // 13
#define ASTRIDE 72         // 144B row stride, ldmatrix conflict-free

__device__ __forceinline__ void mma_f16(float* c, const unsigned* a, const unsigned* b) {
    asm volatile(
        "mma.sync.aligned.m16n8k16.row.col.f32.f16.f16.f32 "
        "{%0,%1,%2,%3}, {%4,%5,%6,%7}, {%8,%9}, {%0,%1,%2,%3};\n"
        : "+f"(c[0]), "+f"(c[1]), "+f"(c[2]), "+f"(c[3])
        : "r"(a[0]), "r"(a[1]), "r"(a[2]), "r"(a[3]), "r"(b[0]), "r"(b[1]));
}

__global__ __launch_bounds__(128, 3) void gemm1_kernel(const float* __restrict__ b1,
                                                       const float* __restrict__ W2) {
    __shared__ __half As[3][64][ASTRIDE];   // 27.6 KB
    __shared__ __half Bs[3][64][ASTRIDE];   // 27.6 KB (total 55.3 KB)

    int tid = threadIdx.x;
    int wid = tid >> 5;
    int lane = tid & 31;
    int warp_m = wid & 1;      // 0..1 -> m offset 32*warp_m
    int warp_n = wid >> 1;     // 0..1 -> n offset 32*warp_n
    int bm = blockIdx.x * 64;
    int bn = blockIdx.y * 64;

    float acc[2][4][4];
#pragma unroll
    for (int i = 0; i < 2; ++i)
#pragma unroll
        for (int j = 0; j < 4; ++j)
#pragma unroll
            for (int k = 0; k < 4; ++k) acc[i][j][k] = 0.f;

#define CPA(dst, src) asm volatile("cp.async.cg.shared.global [%0], [%1], 16;\n" ::"r"(dst), "l"(src))
#define LOAD_STAGE(IT, BUF)                                                      \
    do {                                                                         \
        int k0 = (IT) * GBK;                                                     \
        _Pragma("unroll")                                                        \
        for (int i_ = 0; i_ < 4; ++i_) {                                         \
            int id_ = tid + i_ * 128;                                            \
            int row_ = id_ >> 3, cc_ = id_ & 7;                                  \
            CPA((unsigned)__cvta_generic_to_shared(&As[BUF][row_][cc_ * 8]),     \
                g_A + (size_t)(bm + row_) * KP + k0 + cc_ * 8);                  \
            CPA((unsigned)__cvta_generic_to_shared(&Bs[BUF][row_][cc_ * 8]),     \
                g_B + (size_t)(bn + row_) * KP + k0 + cc_ * 8);                  \
        }                                                                        \
    } while (0)

    LOAD_STAGE(0, 0);
    asm volatile("cp.async.commit_group;\n" ::);
    LOAD_STAGE(1, 1);
    asm volatile("cp.async.commit_group;\n" ::);

    int gid = lane >> 3;   // ldmatrix address group
    int wi = lane & 7;

    for (int it = 0; it < NITER; ++it) {
        int buf = it % 3;
        asm volatile("cp.async.wait_group 1;\n" ::);
        __syncthreads();   // stage `buf` ready; compute of it-1 fully retired

        if (it + 2 < NITER) LOAD_STAGE(it + 2, (it + 2) % 3);
        asm volatile("cp.async.commit_group;\n" ::);

#pragma unroll
        for (int kk = 0; kk < 4; ++kk) {
            unsigned a[2][4];
#pragma unroll
            for (int mf = 0; mf < 2; ++mf) {
                int row = warp_m * 32 + mf * 16 + (gid & 1) * 8 + wi;
                int col = kk * 16 + (gid >> 1) * 8;
                unsigned addr = (unsigned)__cvta_generic_to_shared(&As[buf][row][col]);
                asm volatile(
                    "ldmatrix.sync.aligned.m8n8.x4.shared.b16 {%0,%1,%2,%3}, [%4];\n"
                    : "=r"(a[mf][0]), "=r"(a[mf][1]), "=r"(a[mf][2]), "=r"(a[mf][3])
                    : "r"(addr));
            }
            unsigned b[4][2];
#pragma unroll
            for (int nh = 0; nh < 2; ++nh) {
                int row = warp_n * 32 + nh * 16 + (gid >> 1) * 8 + wi;
                int col = kk * 16 + (gid & 1) * 8;
                unsigned addr = (unsigned)__cvta_generic_to_shared(&Bs[buf][row][col]);
                asm volatile(
                    "ldmatrix.sync.aligned.m8n8.x4.shared.b16 {%0,%1,%2,%3}, [%4];\n"
                    : "=r"(b[2 * nh][0]), "=r"(b[2 * nh][1]),
                      "=r"(b[2 * nh + 1][0]), "=r"(b[2 * nh + 1][1])
                    : "r"(addr));
            }
#pragma unroll
            for (int mf = 0; mf < 2; ++mf)
#pragma unroll
                for (int nf = 0; nf < 4; ++nf) mma_f16(acc[mf][nf], a[mf], b[nf]);
        }
    }

    // ---- fused epilogue: relu(h)+b1 -> partial logits for this 64-col slice
    int nbase = bn + warp_n * 32 + (lane & 3) * 2;
    int slice = blockIdx.y * 2 + warp_n;

    float lp[2][2][10];   // [mf][row-half][output]
#pragma unroll
    for (int mf = 0; mf < 2; ++mf)
#pragma unroll
        for (int rh = 0; rh < 2; ++rh)
#pragma unroll
            for (int o = 0; o < 10; ++o) lp[mf][rh][o] = 0.f;

#pragma unroll
    for (int nf = 0; nf < 4; ++nf) {
        int n = nbase + nf * 8;
        float bx = __ldg(b1 + n), by = __ldg(b1 + n + 1);
        float v[2][2][2];
#pragma unroll
        for (int mf = 0; mf < 2; ++mf) {
            v[mf][0][0] = fmaxf(acc[mf][nf][0] + bx, 0.f);
            v[mf][0][1] = fmaxf(acc[mf][nf][1] + by, 0.f);
            v[mf][1][0] = fmaxf(acc[mf][nf][2] + bx, 0.f);
            v[mf][1][1] = fmaxf(acc[mf][nf][3] + by, 0.f);
        }
#pragma unroll
        for (int o = 0; o < 10; ++o) {
            float w0 = __ldg(W2 + o * 256 + n);
            float w1 = __ldg(W2 + o * 256 + n + 1);
#pragma unroll
            for (int mf = 0; mf < 2; ++mf)
#pragma unroll
                for (int rh = 0; rh < 2; ++rh)
                    lp[mf][rh][o] += v[mf][rh][0] * w0 + v[mf][rh][1] * w1;
        }
    }

    // reduce over the 4 n-lanes (lane&3)
#pragma unroll
    for (int mf = 0; mf < 2; ++mf)
#pragma unroll
        for (int rh = 0; rh < 2; ++rh)
#pragma unroll
            for (int o = 0; o < 10; ++o) {
                lp[mf][rh][o] += __shfl_xor_sync(0xffffffffu, lp[mf][rh][o], 1);
                lp[mf][rh][o] += __shfl_xor_sync(0xffffffffu, lp[mf][rh][o], 2);
            }

    if ((lane & 3) == 0) {
#pragma unroll
        for (int mf = 0; mf < 2; ++mf) {
#pragma unroll
            for (int rh = 0; rh < 2; ++rh) {
                int m = bm + warp_m * 32 + mf * 16 + rh * 8 + (lane >> 2);
                float* dst = g_lpart + ((size_t)slice * BMAX + m) * LPW;
                float4 q0 = make_float4(lp[mf][rh][0], lp[mf][rh][1], lp[mf][rh][2], lp[mf][rh][3]);
                float4 q1 = make_float4(lp[mf][rh][4], lp[mf][rh][5], lp[mf][rh][6], lp[mf][rh][7]);
                float2 q2 = make_float2(lp[mf][rh][8], lp[mf][rh][9]);
                *(float4*)dst = q0;
                *(float4*)(dst + 4) = q1;
                *(float2*)(dst + 8) = q2;
            }
        }
    }
#undef LOAD_STAGE
#undef CPA
}

// ---------------------------------------------------------------------------
// Softmax: logits = sum of 8 partial slices + b2; log_softmax. Thread per row.
// ---------------------------------------------------------------------------
__global__ __launch_bounds__(32) void softmax_kernel(const float* __restrict__ b2,
                                                     float* __restrict__ out, int B) {
    int row = blockIdx.x * 32 + threadIdx.x;
    if (row >= B) return;

    float lg[10];
#pragma unroll
    for (int o = 0; o < 10; ++o) lg[o] = __ldg(b2 + o);

#pragma unroll
    for (int s = 0; s < 8; ++s) {
        const float* p = g_lpart + ((size_t)s * BMAX + row) * LPW;
        float4 a = *(const float4*)p;
        float4 b = *(const float4*)(p + 4);
        float2 c = *(const float2*)(p + 8);
        lg[0] += a.x; lg[1] += a.y; lg[2] += a.z; lg[3] += a.w;
        lg[4] += b.x; lg[5] += b.y; lg[6] += b.z; lg[7] += b.w;
        lg[8] += c.x; lg[9] += c.y;
    }

    float m = lg[0];
#pragma unroll
    for (int o = 1; o < 10; ++o) m = fmaxf(m, lg[o]);
    float sum = 0.f;
#pragma unroll
    for (int o = 0; o < 10; ++o) sum += expf(lg[o] - m);
    float lse = m + logf(sum);

    float* dst = out + (size_t)row * 10;
#pragma unroll
    for (int o = 0; o < 10; ++o) dst[o] = lg[o] - lse;
}

// ---------------------------------------------------------------------------
extern "C" void kernel_launch(void* const* d_in, const int* in_sizes, int n_in,
                              void* d_out, int out_size) {
    const float* x   = (const float*)d_in[0];
    const float* var = (const float*)d_in[1];
    const float* W1  = (const float*)d_in[2];
    const float* b1  = (const float*)d_in[3];
    const float* W2  = (const float*)d_in[4];
    const float* b2  = (const float*)d_in[5];
    float* out = (float*)d_out;

    int B = in_sizes[0] / 784;

    convert_w1_kernel<<<(256 * 196 + 255) / 256, 256>>>(W1);

    int np = B * 196;
    quanv_kernel<<<(np + 255) / 256, 256>>>(x, var, B);

    dim3 g1(B / 64, 4);
    gemm1_kernel<<<g1, 128>>>(b1, W2);

    softmax_kernel<<<(B + 31) / 32, 32>>>(b2, out, B);
}

// round 15
// speedup vs baseline: 3.1717x; 1.0556x over previous
#include <cuda_runtime.h>
#include <cuda_fp16.h>
#include <math.h>

#define BMAX 4096
#define KP 832           // 784 padded to 13*64
#define LPW 12           // padded logit-partial row width (10 -> 12)

// scratch (no allocations allowed)
__device__ __half g_A[BMAX * KP];            // feats fp16, padded
__device__ __half g_B[256 * KP];             // W1 fp16, padded
__device__ float g_lpart[8 * BMAX * LPW];    // per-slice partial logits

__device__ __forceinline__ unsigned pack_half2(__half a, __half b) {
    __half2 t = __halves2half2(a, b);
    return *(unsigned*)&t;
}

// ---------------------------------------------------------------------------
// prep_kernel: blocks [0, qblocks) run quanvolution; blocks [qblocks, ...)
// convert W1 fp32 -> fp16. Independent work fused into one launch.
// ---------------------------------------------------------------------------
__global__ void prep_kernel(const float* __restrict__ x,
                            const float* __restrict__ var,
                            const float* __restrict__ W1,
                            int B, int qblocks) {
    if ((int)blockIdx.x >= qblocks) {
        // ---- W1 conversion ----
        int t = (blockIdx.x - qblocks) * 256 + threadIdx.x;
        if (t >= 256 * 196) return;
        int n = t / 196;
        int kq = t - n * 196;
        int k = kq * 4;

        float4 w = *(const float4*)(W1 + n * 784 + k);
        uint2 hp;
        hp.x = pack_half2(__float2half_rn(w.x), __float2half_rn(w.y));
        hp.y = pack_half2(__float2half_rn(w.z), __float2half_rn(w.w));

        __half* row = g_B + n * KP;
        *(uint2*)(row + k) = hp;
        if (kq < 12) {
            *(uint2*)(row + 784 + kq * 4) = make_uint2(0u, 0u);  // pad 784..831
        }
        return;
    }

    // ---- quanvolution ----
    int idx = blockIdx.x * blockDim.x + threadIdx.x;
    if (idx >= B * 196) return;
    int b = idx / 196;
    int p = idx - b * 196;
    int r = p / 14;
    int c = p - r * 14;

    const float* img = x + b * 784;
    float2 top = *(const float2*)(img + (2 * r) * 28 + 2 * c);
    float2 bot = *(const float2*)(img + (2 * r + 1) * 28 + 2 * c);

    // encoder + depth-0 RY folded (product state is separable)
    float ang[4];
    ang[0] = top.x + __ldg(var + 0);
    ang[1] = top.y + __ldg(var + 1);
    ang[2] = bot.x + __ldg(var + 2);
    ang[3] = bot.y + __ldg(var + 3);

    float ec[4], es[4];
#pragma unroll
    for (int w = 0; w < 4; ++w) __sincosf(0.5f * ang[w], &es[w], &ec[w]);

    float vc[4], vs[4];
#pragma unroll
    for (int w = 0; w < 4; ++w) __sincosf(0.5f * __ldg(var + 4 + w), &vs[w], &vc[w]);

    float A01[4], A23[4];
    A01[0] = ec[0] * ec[1]; A01[1] = ec[0] * es[1];
    A01[2] = es[0] * ec[1]; A01[3] = es[0] * es[1];
    A23[0] = ec[2] * ec[3]; A23[1] = ec[2] * es[3];
    A23[2] = es[2] * ec[3]; A23[3] = es[2] * es[3];

    float st[16];
#pragma unroll
    for (int i = 0; i < 16; ++i) st[i] = A01[i >> 2] * A23[i & 3];

    // CNOT ring (register permutation)
#pragma unroll
    for (int cw = 0; cw < 4; ++cw) {
        int tw = (cw + 1) & 3;
        int cm = 8 >> cw, tm = 8 >> tw;
#pragma unroll
        for (int i = 0; i < 16; ++i) {
            if ((i & cm) && !(i & tm)) {
                int j = i | tm;
                float t = st[i]; st[i] = st[j]; st[j] = t;
            }
        }
    }

    // depth-1 RY layer
#pragma unroll
    for (int w = 0; w < 4; ++w) {
        float cc = vc[w], ss = vs[w];
        int mask = 8 >> w;
#pragma unroll
        for (int i = 0; i < 16; ++i) {
            if (!(i & mask)) {
                int j = i | mask;
                float a = st[i], bb = st[j];
                st[i] = cc * a - ss * bb;
                st[j] = ss * a + cc * bb;
            }
        }
    }

    // CNOT ring
#pragma unroll
    for (int cw = 0; cw < 4; ++cw) {
        int tw = (cw + 1) & 3;
        int cm = 8 >> cw, tm = 8 >> tw;
#pragma unroll
        for (int i = 0; i < 16; ++i) {
            if ((i & cm) && !(i & tm)) {
                int j = i | tm;
                float t = st[i]; st[i] = st[j]; st[j] = t;
            }
        }
    }

    float q[16];
#pragma unroll
    for (int i = 0; i < 16; ++i) q[i] = st[i] * st[i];

    float fo[4];
#pragma unroll
    for (int w = 0; w < 4; ++w) {
        int m = 8 >> w;
        float acc = 0.f;
#pragma unroll
        for (int i = 0; i < 16; ++i) acc += (i & m) ? -q[i] : q[i];
        fo[w] = acc;
    }

    uint2 hp;
    hp.x = pack_half2(__float2half_rn(fo[0]), __float2half_rn(fo[1]));
    hp.y = pack_half2(__float2half_rn(fo[2]), __float2half_rn(fo[3]));

    __half* row = g_A + (size_t)b * KP;
    *(uint2*)(row + p * 4) = hp;
    if (p < 12) {
        *(uint2*)(row + 784 + p * 4) = make_uint2(0u, 0u);  // pad 784..831
    }
}

// ---------------------------------------------------------------------------
// Tensor-core GEMM1 + fused logit partials.
// h = relu(A @ B^T + b1); lpart[slice][m][o] = sum_{n in slice} h[m][n]*W2[o][n]
// BM=64, BN=64, BK=64, 4 warps (2x2), warp tile 32x32 via m16n8k16 mma.
// 3-stage cp.async pipeline, one __syncthreads per iter, grid (B/64, 4).
// ---------------------------------------------------------------------------
#define GBK 64
#define NITER (KP / GBK)   // 13
#define ASTRIDE 72         // 144B row stride, ldmatrix conflict-free

__device__ __forceinline__ void mma_f16(float* c, const unsigned* a, const unsigned* b) {
    asm volatile(
        "mma.sync.aligned.m16n8k16.row.col.f32.f16.f16.f32 "
        "{%0,%1,%2,%3}, {%4,%5,%6,%7}, {%8,%9}, {%0,%1,%2,%3};\n"
        : "+f"(c[0]), "+f"(c[1]), "+f"(c[2]), "+f"(c[3])
        : "r"(a[0]), "r"(a[1]), "r"(a[2]), "r"(a[3]), "r"(b[0]), "r"(b[1]));
}

__global__ __launch_bounds__(128, 3) void gemm1_kernel(const float* __restrict__ b1,
                                                       const float* __restrict__ W2) {
    __shared__ __half As[3][64][ASTRIDE];   // 27.6 KB
    __shared__ __half Bs[3][64][ASTRIDE];   // 27.6 KB (total 55.3 KB)

    int tid = threadIdx.x;
    int wid = tid >> 5;
    int lane = tid & 31;
    int warp_m = wid & 1;      // 0..1 -> m offset 32*warp_m
    int warp_n = wid >> 1;     // 0..1 -> n offset 32*warp_n
    int bm = blockIdx.x * 64;
    int bn = blockIdx.y * 64;

    float acc[2][4][4];
#pragma unroll
    for (int i = 0; i < 2; ++i)
#pragma unroll
        for (int j = 0; j < 4; ++j)
#pragma unroll
            for (int k = 0; k < 4; ++k) acc[i][j][k] = 0.f;

#define CPA(dst, src) asm volatile("cp.async.cg.shared.global [%0], [%1], 16;\n" ::"r"(dst), "l"(src))
#define LOAD_STAGE(IT, BUF)                                                      \
    do {                                                                         \
        int k0 = (IT) * GBK;                                                     \
        _Pragma("unroll")                                                        \
        for (int i_ = 0; i_ < 4; ++i_) {                                         \
            int id_ = tid + i_ * 128;                                            \
            int row_ = id_ >> 3, cc_ = id_ & 7;                                  \
            CPA((unsigned)__cvta_generic_to_shared(&As[BUF][row_][cc_ * 8]),     \
                g_A + (size_t)(bm + row_) * KP + k0 + cc_ * 8);                  \
            CPA((unsigned)__cvta_generic_to_shared(&Bs[BUF][row_][cc_ * 8]),     \
                g_B + (size_t)(bn + row_) * KP + k0 + cc_ * 8);                  \
        }                                                                        \
    } while (0)

    LOAD_STAGE(0, 0);
    asm volatile("cp.async.commit_group;\n" ::);
    LOAD_STAGE(1, 1);
    asm volatile("cp.async.commit_group;\n" ::);

    int gid = lane >> 3;   // ldmatrix address group
    int wi = lane & 7;

    for (int it = 0; it < NITER; ++it) {
        int buf = it % 3;
        asm volatile("cp.async.wait_group 1;\n" ::);
        __syncthreads();   // stage `buf` ready; compute of it-1 fully retired

        if (it + 2 < NITER) LOAD_STAGE(it + 2, (it + 2) % 3);
        asm volatile("cp.async.commit_group;\n" ::);

#pragma unroll
        for (int kk = 0; kk < 4; ++kk) {
            unsigned a[2][4];
#pragma unroll
            for (int mf = 0; mf < 2; ++mf) {
                int row = warp_m * 32 + mf * 16 + (gid & 1) * 8 + wi;
                int col = kk * 16 + (gid >> 1) * 8;
                unsigned addr = (unsigned)__cvta_generic_to_shared(&As[buf][row][col]);
                asm volatile(
                    "ldmatrix.sync.aligned.m8n8.x4.shared.b16 {%0,%1,%2,%3}, [%4];\n"
                    : "=r"(a[mf][0]), "=r"(a[mf][1]), "=r"(a[mf][2]), "=r"(a[mf][3])
                    : "r"(addr));
            }
            unsigned b[4][2];
#pragma unroll
            for (int nh = 0; nh < 2; ++nh) {
                int row = warp_n * 32 + nh * 16 + (gid >> 1) * 8 + wi;
                int col = kk * 16 + (gid & 1) * 8;
                unsigned addr = (unsigned)__cvta_generic_to_shared(&Bs[buf][row][col]);
                asm volatile(
                    "ldmatrix.sync.aligned.m8n8.x4.shared.b16 {%0,%1,%2,%3}, [%4];\n"
                    : "=r"(b[2 * nh][0]), "=r"(b[2 * nh][1]),
                      "=r"(b[2 * nh + 1][0]), "=r"(b[2 * nh + 1][1])
                    : "r"(addr));
            }
#pragma unroll
            for (int mf = 0; mf < 2; ++mf)
#pragma unroll
                for (int nf = 0; nf < 4; ++nf) mma_f16(acc[mf][nf], a[mf], b[nf]);
        }
    }

    // ---- fused epilogue: relu(h)+b1 -> partial logits for this 64-col slice
    int nbase = bn + warp_n * 32 + (lane & 3) * 2;
    int slice = blockIdx.y * 2 + warp_n;

    float lp[2][2][10];   // [mf][row-half][output]
#pragma unroll
    for (int mf = 0; mf < 2; ++mf)
#pragma unroll
        for (int rh = 0; rh < 2; ++rh)
#pragma unroll
            for (int o = 0; o < 10; ++o) lp[mf][rh][o] = 0.f;

#pragma unroll
    for (int nf = 0; nf < 4; ++nf) {
        int n = nbase + nf * 8;
        float bx = __ldg(b1 + n), by = __ldg(b1 + n + 1);
        float v[2][2][2];
#pragma unroll
        for (int mf = 0; mf < 2; ++mf) {
            v[mf][0][0] = fmaxf(acc[mf][nf][0] + bx, 0.f);
            v[mf][0][1] = fmaxf(acc[mf][nf][1] + by, 0.f);
            v[mf][1][0] = fmaxf(acc[mf][nf][2] + bx, 0.f);
            v[mf][1][1] = fmaxf(acc[mf][nf][3] + by, 0.f);
        }
#pragma unroll
        for (int o = 0; o < 10; ++o) {
            float w0 = __ldg(W2 + o * 256 + n);
            float w1 = __ldg(W2 + o * 256 + n + 1);
#pragma unroll
            for (int mf = 0; mf < 2; ++mf)
#pragma unroll
                for (int rh = 0; rh < 2; ++rh)
                    lp[mf][rh][o] += v[mf][rh][0] * w0 + v[mf][rh][1] * w1;
        }
    }

    // reduce over the 4 n-lanes (lane&3)
#pragma unroll
    for (int mf = 0; mf < 2; ++mf)
#pragma unroll
        for (int rh = 0; rh < 2; ++rh)
#pragma unroll
            for (int o = 0; o < 10; ++o) {
                lp[mf][rh][o] += __shfl_xor_sync(0xffffffffu, lp[mf][rh][o], 1);
                lp[mf][rh][o] += __shfl_xor_sync(0xffffffffu, lp[mf][rh][o], 2);
            }

    if ((lane & 3) == 0) {
#pragma unroll
        for (int mf = 0; mf < 2; ++mf) {
#pragma unroll
            for (int rh = 0; rh < 2; ++rh) {
                int m = bm + warp_m * 32 + mf * 16 + rh * 8 + (lane >> 2);
                float* dst = g_lpart + ((size_t)slice * BMAX + m) * LPW;
                float4 q0 = make_float4(lp[mf][rh][0], lp[mf][rh][1], lp[mf][rh][2], lp[mf][rh][3]);
                float4 q1 = make_float4(lp[mf][rh][4], lp[mf][rh][5], lp[mf][rh][6], lp[mf][rh][7]);
                float2 q2 = make_float2(lp[mf][rh][8], lp[mf][rh][9]);
                *(float4*)dst = q0;
                *(float4*)(dst + 4) = q1;
                *(float2*)(dst + 8) = q2;
            }
        }
    }
#undef LOAD_STAGE
#undef CPA
}

// ---------------------------------------------------------------------------
// Softmax: 8 lanes per row (one per slice), xor-shuffle reduce, log_softmax.
// Output stores use float2 only: out row stride is 40B (8B-aligned, NOT 16B).
// ---------------------------------------------------------------------------
__global__ __launch_bounds__(256) void softmax_kernel(const float* __restrict__ b2,
                                                      float* __restrict__ out, int B) {
    int t = blockIdx.x * 256 + threadIdx.x;
    int row = t >> 3;
    int s = t & 7;
    if (row >= B) return;

    const float* p = g_lpart + ((size_t)s * BMAX + row) * LPW;
    float4 a = *(const float4*)p;
    float4 b = *(const float4*)(p + 4);
    float2 c = *(const float2*)(p + 8);
    float lg[10] = {a.x, a.y, a.z, a.w, b.x, b.y, b.z, b.w, c.x, c.y};

#pragma unroll
    for (int off = 1; off < 8; off <<= 1)
#pragma unroll
        for (int o = 0; o < 10; ++o)
            lg[o] += __shfl_xor_sync(0xffffffffu, lg[o], off);

    if (s == 0) {
#pragma unroll
        for (int o = 0; o < 10; ++o) lg[o] += __ldg(b2 + o);

        float m = lg[0];
#pragma unroll
        for (int o = 1; o < 10; ++o) m = fmaxf(m, lg[o]);
        float sum = 0.f;
#pragma unroll
        for (int o = 0; o < 10; ++o) sum += expf(lg[o] - m);
        float lse = m + logf(sum);

        float* dst = out + (size_t)row * 10;
#pragma unroll
        for (int o = 0; o < 10; o += 2) {
            float2 q = make_float2(lg[o] - lse, lg[o + 1] - lse);
            *(float2*)(dst + o) = q;   // 8B-aligned for any row
        }
    }
}

// ---------------------------------------------------------------------------
extern "C" void kernel_launch(void* const* d_in, const int* in_sizes, int n_in,
                              void* d_out, int out_size) {
    const float* x   = (const float*)d_in[0];
    const float* var = (const float*)d_in[1];
    const float* W1  = (const float*)d_in[2];
    const float* b1  = (const float*)d_in[3];
    const float* W2  = (const float*)d_in[4];
    const float* b2  = (const float*)d_in[5];
    float* out = (float*)d_out;

    int B = in_sizes[0] / 784;

    int qblocks = (B * 196 + 255) / 256;          // quanv blocks
    int cblocks = (256 * 196 + 255) / 256;        // W1-convert blocks
    prep_kernel<<<qblocks + cblocks, 256>>>(x, var, W1, B, qblocks);

    dim3 g1(B / 64, 4);
    gemm1_kernel<<<g1, 128>>>(b1, W2);

    softmax_kernel<<<(B * 8 + 255) / 256, 256>>>(b2, out, B);
}

// round 16
// speedup vs baseline: 3.2041x; 1.0102x over previous
#include <cuda_runtime.h>
#include <cuda_fp16.h>
#include <math.h>

#define BMAX 4096
#define KP 832           // 784 padded to 13*64
#define LPW 12           // padded logit-partial row width (10 -> 12)

// scratch (no allocations allowed)
__device__ __half g_A[BMAX * KP];            // feats fp16, padded
__device__ __half g_B[256 * KP];             // W1 fp16, padded
__device__ float g_lpart[8 * BMAX * LPW];    // per-slice partial logits

__device__ __forceinline__ unsigned pack_half2(__half a, __half b) {
    __half2 t = __halves2half2(a, b);
    return *(unsigned*)&t;
}

// ---------------------------------------------------------------------------
// prep_kernel: blocks [0, qblocks) run quanvolution; blocks [qblocks, ...)
// convert W1 fp32 -> fp16. Independent work fused into one launch.
// ---------------------------------------------------------------------------
__global__ void prep_kernel(const float* __restrict__ x,
                            const float* __restrict__ var,
                            const float* __restrict__ W1,
                            int B, int qblocks) {
    if ((int)blockIdx.x >= qblocks) {
        // ---- W1 conversion ----
        int t = (blockIdx.x - qblocks) * 256 + threadIdx.x;
        if (t >= 256 * 196) return;
        int n = t / 196;
        int kq = t - n * 196;
        int k = kq * 4;

        float4 w = *(const float4*)(W1 + n * 784 + k);
        uint2 hp;
        hp.x = pack_half2(__float2half_rn(w.x), __float2half_rn(w.y));
        hp.y = pack_half2(__float2half_rn(w.z), __float2half_rn(w.w));

        __half* row = g_B + n * KP;
        *(uint2*)(row + k) = hp;
        if (kq < 12) {
            *(uint2*)(row + 784 + kq * 4) = make_uint2(0u, 0u);  // pad 784..831
        }
        return;
    }

    // ---- quanvolution ----
    // per-block var staging: offsets var[0..3], sin/cos of half var[4..7]
    __shared__ float sv[12];
    if (threadIdx.x < 4) {
        sv[threadIdx.x] = __ldg(var + threadIdx.x);
        float h = 0.5f * __ldg(var + 4 + threadIdx.x);
        sv[4 + threadIdx.x] = __sinf(h);
        sv[8 + threadIdx.x] = __cosf(h);
    }
    __syncthreads();

    int idx = blockIdx.x * blockDim.x + threadIdx.x;
    if (idx >= B * 196) return;
    int b = idx / 196;
    int p = idx - b * 196;
    int r = p / 14;
    int c = p - r * 14;

    const float* img = x + b * 784;
    float2 top = *(const float2*)(img + (2 * r) * 28 + 2 * c);
    float2 bot = *(const float2*)(img + (2 * r + 1) * 28 + 2 * c);

    // encoder + depth-0 RY folded (product state is separable)
    float ang[4];
    ang[0] = top.x + sv[0];
    ang[1] = top.y + sv[1];
    ang[2] = bot.x + sv[2];
    ang[3] = bot.y + sv[3];

    float ec[4], es[4];
#pragma unroll
    for (int w = 0; w < 4; ++w) __sincosf(0.5f * ang[w], &es[w], &ec[w]);

    float vs[4], vc[4];
#pragma unroll
    for (int w = 0; w < 4; ++w) { vs[w] = sv[4 + w]; vc[w] = sv[8 + w]; }

    float A01[4], A23[4];
    A01[0] = ec[0] * ec[1]; A01[1] = ec[0] * es[1];
    A01[2] = es[0] * ec[1]; A01[3] = es[0] * es[1];
    A23[0] = ec[2] * ec[3]; A23[1] = ec[2] * es[3];
    A23[2] = es[2] * ec[3]; A23[3] = es[2] * es[3];

    float st[16];
#pragma unroll
    for (int i = 0; i < 16; ++i) st[i] = A01[i >> 2] * A23[i & 3];

    // CNOT ring (register permutation, free)
#pragma unroll
    for (int cw = 0; cw < 4; ++cw) {
        int tw = (cw + 1) & 3;
        int cm = 8 >> cw, tm = 8 >> tw;
#pragma unroll
        for (int i = 0; i < 16; ++i) {
            if ((i & cm) && !(i & tm)) {
                int j = i | tm;
                float t = st[i]; st[i] = st[j]; st[j] = t;
            }
        }
    }

    // depth-1 RY layer
#pragma unroll
    for (int w = 0; w < 4; ++w) {
        float cc = vc[w], ss = vs[w];
        int mask = 8 >> w;
#pragma unroll
        for (int i = 0; i < 16; ++i) {
            if (!(i & mask)) {
                int j = i | mask;
                float a = st[i], bb = st[j];
                st[i] = cc * a - ss * bb;
                st[j] = ss * a + cc * bb;
            }
        }
    }

    // CNOT ring (register permutation, free)
#pragma unroll
    for (int cw = 0; cw < 4; ++cw) {
        int tw = (cw + 1) & 3;
        int cm = 8 >> cw, tm = 8 >> tw;
#pragma unroll
        for (int i = 0; i < 16; ++i) {
            if ((i & cm) && !(i & tm)) {
                int j = i | tm;
                float t = st[i]; st[i] = st[j]; st[j] = t;
            }
        }
    }

    float q[16];
#pragma unroll
    for (int i = 0; i < 16; ++i) q[i] = st[i] * st[i];

    // shared-subtree sums: f_w = norm - 2*S_w, S_w = sum over bit_w-set q's
    float t1[8], t2[4];
#pragma unroll
    for (int j = 0; j < 8; ++j) t1[j] = q[2 * j] + q[2 * j + 1];
#pragma unroll
    for (int j = 0; j < 4; ++j) t2[j] = t1[2 * j] + t1[2 * j + 1];
    float norm = (t2[0] + t2[1]) + (t2[2] + t2[3]);
    float S0 = t2[2] + t2[3];                       // bit3 (wire 0)
    float S1 = t2[1] + t2[3];                       // bit2 (wire 1)
    float S2 = (t1[1] + t1[3]) + (t1[5] + t1[7]);   // bit1 (wire 2)
    float S3 = ((q[1] + q[3]) + (q[5] + q[7])) +
               ((q[9] + q[11]) + (q[13] + q[15]));  // bit0 (wire 3)

    float fo[4];
    fo[0] = fmaf(-2.f, S0, norm);
    fo[1] = fmaf(-2.f, S1, norm);
    fo[2] = fmaf(-2.f, S2, norm);
    fo[3] = fmaf(-2.f, S3, norm);

    uint2 hp;
    hp.x = pack_half2(__float2half_rn(fo[0]), __float2half_rn(fo[1]));
    hp.y = pack_half2(__float2half_rn(fo[2]), __float2half_rn(fo[3]));

    __half* row = g_A + (size_t)b * KP;
    *(uint2*)(row + p * 4) = hp;
    if (p < 12) {
        *(uint2*)(row + 784 + p * 4) = make_uint2(0u, 0u);  // pad 784..831
    }
}

// ---------------------------------------------------------------------------
// Tensor-core GEMM1 + fused logit partials.
// h = relu(A @ B^T + b1); lpart[slice][m][o] = sum_{n in slice} h[m][n]*W2[o][n]
// BM=64, BN=64, BK=64, 4 warps (2x2), warp tile 32x32 via m16n8k16 mma.
// 3-stage cp.async pipeline, one __syncthreads per iter, grid (B/64, 4).
// ---------------------------------------------------------------------------
#define GBK 64
#define NITER (KP / GBK)   // 13
#define ASTRIDE 72         // 144B row stride, ldmatrix conflict-free

__device__ __forceinline__ void mma_f16(float* c, const unsigned* a, const unsigned* b) {
    asm volatile(
        "mma.sync.aligned.m16n8k16.row.col.f32.f16.f16.f32 "
        "{%0,%1,%2,%3}, {%4,%5,%6,%7}, {%8,%9}, {%0,%1,%2,%3};\n"
        : "+f"(c[0]), "+f"(c[1]), "+f"(c[2]), "+f"(c[3])
        : "r"(a[0]), "r"(a[1]), "r"(a[2]), "r"(a[3]), "r"(b[0]), "r"(b[1]));
}

__global__ __launch_bounds__(128, 3) void gemm1_kernel(const float* __restrict__ b1,
                                                       const float* __restrict__ W2) {
    __shared__ __half As[3][64][ASTRIDE];   // 27.6 KB
    __shared__ __half Bs[3][64][ASTRIDE];   // 27.6 KB (total 55.3 KB)

    int tid = threadIdx.x;
    int wid = tid >> 5;
    int lane = tid & 31;
    int warp_m = wid & 1;      // 0..1 -> m offset 32*warp_m
    int warp_n = wid >> 1;     // 0..1 -> n offset 32*warp_n
    int bm = blockIdx.x * 64;
    int bn = blockIdx.y * 64;

    float acc[2][4][4];
#pragma unroll
    for (int i = 0; i < 2; ++i)
#pragma unroll
        for (int j = 0; j < 4; ++j)
#pragma unroll
            for (int k = 0; k < 4; ++k) acc[i][j][k] = 0.f;

#define CPA(dst, src) asm volatile("cp.async.cg.shared.global [%0], [%1], 16;\n" ::"r"(dst), "l"(src))
#define LOAD_STAGE(IT, BUF)                                                      \
    do {                                                                         \
        int k0 = (IT) * GBK;                                                     \
        _Pragma("unroll")                                                        \
        for (int i_ = 0; i_ < 4; ++i_) {                                         \
            int id_ = tid + i_ * 128;                                            \
            int row_ = id_ >> 3, cc_ = id_ & 7;                                  \
            CPA((unsigned)__cvta_generic_to_shared(&As[BUF][row_][cc_ * 8]),     \
                g_A + (size_t)(bm + row_) * KP + k0 + cc_ * 8);                  \
            CPA((unsigned)__cvta_generic_to_shared(&Bs[BUF][row_][cc_ * 8]),     \
                g_B + (size_t)(bn + row_) * KP + k0 + cc_ * 8);                  \
        }                                                                        \
    } while (0)

    LOAD_STAGE(0, 0);
    asm volatile("cp.async.commit_group;\n" ::);
    LOAD_STAGE(1, 1);
    asm volatile("cp.async.commit_group;\n" ::);

    int gid = lane >> 3;   // ldmatrix address group
    int wi = lane & 7;

    for (int it = 0; it < NITER; ++it) {
        int buf = it % 3;
        asm volatile("cp.async.wait_group 1;\n" ::);
        __syncthreads();   // stage `buf` ready; compute of it-1 fully retired

        if (it + 2 < NITER) LOAD_STAGE(it + 2, (it + 2) % 3);
        asm volatile("cp.async.commit_group;\n" ::);

#pragma unroll
        for (int kk = 0; kk < 4; ++kk) {
            unsigned a[2][4];
#pragma unroll
            for (int mf = 0; mf < 2; ++mf) {
                int row = warp_m * 32 + mf * 16 + (gid & 1) * 8 + wi;
                int col = kk * 16 + (gid >> 1) * 8;
                unsigned addr = (unsigned)__cvta_generic_to_shared(&As[buf][row][col]);
                asm volatile(
                    "ldmatrix.sync.aligned.m8n8.x4.shared.b16 {%0,%1,%2,%3}, [%4];\n"
                    : "=r"(a[mf][0]), "=r"(a[mf][1]), "=r"(a[mf][2]), "=r"(a[mf][3])
                    : "r"(addr));
            }
            unsigned b[4][2];
#pragma unroll
            for (int nh = 0; nh < 2; ++nh) {
                int row = warp_n * 32 + nh * 16 + (gid >> 1) * 8 + wi;
                int col = kk * 16 + (gid & 1) * 8;
                unsigned addr = (unsigned)__cvta_generic_to_shared(&Bs[buf][row][col]);
                asm volatile(
                    "ldmatrix.sync.aligned.m8n8.x4.shared.b16 {%0,%1,%2,%3}, [%4];\n"
                    : "=r"(b[2 * nh][0]), "=r"(b[2 * nh][1]),
                      "=r"(b[2 * nh + 1][0]), "=r"(b[2 * nh + 1][1])
                    : "r"(addr));
            }
#pragma unroll
            for (int mf = 0; mf < 2; ++mf)
#pragma unroll
                for (int nf = 0; nf < 4; ++nf) mma_f16(acc[mf][nf], a[mf], b[nf]);
        }
    }

    // ---- fused epilogue: relu(h)+b1 -> partial logits for this 64-col slice
    int nbase = bn + warp_n * 32 + (lane & 3) * 2;
    int slice = blockIdx.y * 2 + warp_n;

    float lp[2][2][10];   // [mf][row-half][output]
#pragma unroll
    for (int mf = 0; mf < 2; ++mf)
#pragma unroll
        for (int rh = 0; rh < 2; ++rh)
#pragma unroll
            for (int o = 0; o < 10; ++o) lp[mf][rh][o] = 0.f;

#pragma unroll
    for (int nf = 0; nf < 4; ++nf) {
        int n = nbase + nf * 8;
        float bx = __ldg(b1 + n), by = __ldg(b1 + n + 1);
        float v[2][2][2];
#pragma unroll
        for (int mf = 0; mf < 2; ++mf) {
            v[mf][0][0] = fmaxf(acc[mf][nf][0] + bx, 0.f);
            v[mf][0][1] = fmaxf(acc[mf][nf][1] + by, 0.f);
            v[mf][1][0] = fmaxf(acc[mf][nf][2] + bx, 0.f);
            v[mf][1][1] = fmaxf(acc[mf][nf][3] + by, 0.f);
        }
#pragma unroll
        for (int o = 0; o < 10; ++o) {
            float w0 = __ldg(W2 + o * 256 + n);
            float w1 = __ldg(W2 + o * 256 + n + 1);
#pragma unroll
            for (int mf = 0; mf < 2; ++mf)
#pragma unroll
                for (int rh = 0; rh < 2; ++rh)
                    lp[mf][rh][o] += v[mf][rh][0] * w0 + v[mf][rh][1] * w1;
        }
    }

    // reduce over the 4 n-lanes (lane&3)
#pragma unroll
    for (int mf = 0; mf < 2; ++mf)
#pragma unroll
        for (int rh = 0; rh < 2; ++rh)
#pragma unroll
            for (int o = 0; o < 10; ++o) {
                lp[mf][rh][o] += __shfl_xor_sync(0xffffffffu, lp[mf][rh][o], 1);
                lp[mf][rh][o] += __shfl_xor_sync(0xffffffffu, lp[mf][rh][o], 2);
            }

    if ((lane & 3) == 0) {
#pragma unroll
        for (int mf = 0; mf < 2; ++mf) {
#pragma unroll
            for (int rh = 0; rh < 2; ++rh) {
                int m = bm + warp_m * 32 + mf * 16 + rh * 8 + (lane >> 2);
                float* dst = g_lpart + ((size_t)slice * BMAX + m) * LPW;
                float4 q0 = make_float4(lp[mf][rh][0], lp[mf][rh][1], lp[mf][rh][2], lp[mf][rh][3]);
                float4 q1 = make_float4(lp[mf][rh][4], lp[mf][rh][5], lp[mf][rh][6], lp[mf][rh][7]);
                float2 q2 = make_float2(lp[mf][rh][8], lp[mf][rh][9]);
                *(float4*)dst = q0;
                *(float4*)(dst + 4) = q1;
                *(float2*)(dst + 8) = q2;
            }
        }
    }
#undef LOAD_STAGE
#undef CPA
}

// ---------------------------------------------------------------------------
// Softmax: 8 lanes per row (one per slice), xor-shuffle reduce, log_softmax.
// Output stores use float2 only: out row stride is 40B (8B-aligned, NOT 16B).
// ---------------------------------------------------------------------------
__global__ __launch_bounds__(256) void softmax_kernel(const float* __restrict__ b2,
                                                      float* __restrict__ out, int B) {
    int t = blockIdx.x * 256 + threadIdx.x;
    int row = t >> 3;
    int s = t & 7;
    if (row >= B) return;

    const float* p = g_lpart + ((size_t)s * BMAX + row) * LPW;
    float4 a = *(const float4*)p;
    float4 b = *(const float4*)(p + 4);
    float2 c = *(const float2*)(p + 8);
    float lg[10] = {a.x, a.y, a.z, a.w, b.x, b.y, b.z, b.w, c.x, c.y};

#pragma unroll
    for (int off = 1; off < 8; off <<= 1)
#pragma unroll
        for (int o = 0; o < 10; ++o)
            lg[o] += __shfl_xor_sync(0xffffffffu, lg[o], off);

    if (s == 0) {
#pragma unroll
        for (int o = 0; o < 10; ++o) lg[o] += __ldg(b2 + o);

        float m = lg[0];
#pragma unroll
        for (int o = 1; o < 10; ++o) m = fmaxf(m, lg[o]);
        float sum = 0.f;
#pragma unroll
        for (int o = 0; o < 10; ++o) sum += expf(lg[o] - m);
        float lse = m + logf(sum);

        float* dst = out + (size_t)row * 10;
#pragma unroll
        for (int o = 0; o < 10; o += 2) {
            float2 q = make_float2(lg[o] - lse, lg[o + 1] - lse);
            *(float2*)(dst + o) = q;   // 8B-aligned for any row
        }
    }
}

// ---------------------------------------------------------------------------
extern "C" void kernel_launch(void* const* d_in, const int* in_sizes, int n_in,
                              void* d_out, int out_size) {
    const float* x   = (const float*)d_in[0];
    const float* var = (const float*)d_in[1];
    const float* W1  = (const float*)d_in[2];
    const float* b1  = (const float*)d_in[3];
    const float* W2  = (const float*)d_in[4];
    const float* b2  = (const float*)d_in[5];
    float* out = (float*)d_out;

    int B = in_sizes[0] / 784;

    int qblocks = (B * 196 + 255) / 256;          // quanv blocks
    int cblocks = (256 * 196 + 255) / 256;        // W1-convert blocks
    prep_kernel<<<qblocks + cblocks, 256>>>(x, var, W1, B, qblocks);

    dim3 g1(B / 64, 4);
    gemm1_kernel<<<g1, 128>>>(b1, W2);

    softmax_kernel<<<(B * 8 + 255) / 256, 256>>>(b2, out, B);
}